// round 9
// baseline (speedup 1.0000x reference)
#include <cuda_runtime.h>
#include <mma.h>
#include <cstdint>

using namespace nvcuda;

#define Bp 32
#define Np 1024
#define Mp 1024
#define Dp 128

// Scratch (device globals; allocation is forbidden everywhere)
__device__ float g_Xc[Bp * Np * Dp];            // X * tanh(W@A^T+b)  [b][n][d] (fp32)
__device__ float g_Xr[Bp * Np * Dp];            // tf32-rounded Xs
__device__ float g_Yr[Bp * Mp * Dp];            // tf32-rounded Ys
__device__ float g_P[(size_t)Bp * Np * Mp];     // P = tf32r(1+e^z)   [b][n][m]
__device__ float g_rs[Bp * Np];                 // row sums of rounded P
__device__ float g_cs[Bp * Mp];                 // col sums of rounded P

// ---------------------------------------------------------------------------
__device__ __forceinline__ uint32_t s2u(const void* p) {
    uint32_t a;
    asm("{ .reg .u64 t; cvta.to.shared.u64 t, %1; cvt.u32.u64 %0, t; }"
        : "=r"(a) : "l"(p));
    return a;
}
__device__ __forceinline__ void cpa16(uint32_t d, const void* s) {
    asm volatile("cp.async.cg.shared.global [%0], [%1], 16;"
                 :: "r"(d), "l"(s) : "memory");
}
#define CP_COMMIT() asm volatile("cp.async.commit_group;" ::: "memory")
#define CP_WAIT1()  asm volatile("cp.async.wait_group 1;" ::: "memory")
#define CP_WAIT0()  asm volatile("cp.async.wait_group 0;" ::: "memory")

__device__ __forceinline__ float tf32r(float x) {
    return wmma::__float_to_tf32(x);
}

__device__ __forceinline__ unsigned long long fma2(unsigned long long a,
                                                   unsigned long long b,
                                                   unsigned long long c) {
    unsigned long long d;
    asm("fma.rn.f32x2 %0, %1, %2, %3;" : "=l"(d) : "l"(a), "l"(b), "l"(c));
    return d;
}
__device__ __forceinline__ float2 up2(unsigned long long u) {
    float2 f;
    asm("mov.b64 {%0, %1}, %2;" : "=f"(f.x), "=f"(f.y) : "l"(u));
    return f;
}
__device__ __forceinline__ unsigned long long dup2(float x) {
    unsigned long long d;
    asm("mov.b64 %0, {%1, %1};" : "=l"(d) : "f"(x));
    return d;
}

// wmma ring (attn): stage f at f*BUFSZ floats; A @ +0, B @ +4352
#define BUFSZ 8704
#define SMEM_DYN (3 * BUFSZ * 4)   // 104448 bytes

typedef wmma::fragment<wmma::matrix_a, 16, 16, 8, wmma::precision::tf32,
                       wmma::row_major> FragAR;
typedef wmma::fragment<wmma::matrix_a, 16, 16, 8, wmma::precision::tf32,
                       wmma::col_major> FragAC;
typedef wmma::fragment<wmma::matrix_b, 16, 16, 8, wmma::precision::tf32,
                       wmma::row_major> FragBR;
typedef wmma::fragment<wmma::accumulator, 16, 16, 8, float> FragC;

// ---------------------------------------------------------------------------
__global__ void k_zero() {
    int i = blockIdx.x * 256 + threadIdx.x;
    g_rs[i] = 0.f;
    g_cs[i] = 0.f;
}

// tf32-rounded copies of Xs and Ys. 4,194,304 elems / (256*4) = 4096 blocks.
__global__ void k_prep(const float* __restrict__ Xs, const float* __restrict__ Ys) {
    size_t i = ((size_t)blockIdx.x * 256 + threadIdx.x) * 4;
    float4 x = *(const float4*)(Xs + i);
    float4 y = *(const float4*)(Ys + i);
    *(float4*)(g_Xr + i) =
        make_float4(tf32r(x.x), tf32r(x.y), tf32r(x.z), tf32r(x.w));
    *(float4*)(g_Yr + i) =
        make_float4(tf32r(y.x), tf32r(y.y), tf32r(y.z), tf32r(y.w));
}

// ---------------------------------------------------------------------------
// K1: Xc[r][e] = Xs[r][e] * tanh( sum_d W[r][d]*Aw[e][d] + Ab[e] )  (verified)
// ---------------------------------------------------------------------------
__global__ __launch_bounds__(256) void k_coeff(const float* __restrict__ W,
                                               const float* __restrict__ Aw,
                                               const float* __restrict__ Ab,
                                               const float* __restrict__ Xs) {
    const int tx = threadIdx.x, ty = threadIdx.y;
    const int tid = ty * 16 + tx;
    const int r0 = blockIdx.x * 64;

    __shared__ __align__(16) float Ws[64][32];
    __shared__ __align__(16) float Awt[32][132];

    float acc[4][8];
#pragma unroll
    for (int i = 0; i < 4; i++)
#pragma unroll
        for (int j = 0; j < 8; j++) acc[i][j] = 0.f;

    for (int k0 = 0; k0 < Dp; k0 += 32) {
#pragma unroll
        for (int it = 0; it < 2; it++) {
            int id = tid + it * 256;
            int r = id >> 3, q = id & 7;
            *(float4*)&Ws[r][q * 4] =
                *(const float4*)(W + (size_t)(r0 + r) * Dp + k0 + q * 4);
        }
#pragma unroll
        for (int it = 0; it < 4; it++) {
            int id = tid + it * 256;
            int e = id >> 3, q = id & 7;
            float4 v = *(const float4*)(Aw + (size_t)e * Dp + k0 + q * 4);
            Awt[q * 4 + 0][e] = v.x;
            Awt[q * 4 + 1][e] = v.y;
            Awt[q * 4 + 2][e] = v.z;
            Awt[q * 4 + 3][e] = v.w;
        }
        __syncthreads();
#pragma unroll
        for (int k = 0; k < 32; k++) {
            float w0 = Ws[ty * 4 + 0][k];
            float w1 = Ws[ty * 4 + 1][k];
            float w2 = Ws[ty * 4 + 2][k];
            float w3 = Ws[ty * 4 + 3][k];
            float4 a0 = *(const float4*)&Awt[k][tx * 8];
            float4 a1 = *(const float4*)&Awt[k][tx * 8 + 4];
            float av[8] = {a0.x, a0.y, a0.z, a0.w, a1.x, a1.y, a1.z, a1.w};
#pragma unroll
            for (int j = 0; j < 8; j++) {
                acc[0][j] = fmaf(w0, av[j], acc[0][j]);
                acc[1][j] = fmaf(w1, av[j], acc[1][j]);
                acc[2][j] = fmaf(w2, av[j], acc[2][j]);
                acc[3][j] = fmaf(w3, av[j], acc[3][j]);
            }
        }
        __syncthreads();
    }

    float abv[8];
    *(float4*)&abv[0] = *(const float4*)(Ab + tx * 8);
    *(float4*)&abv[4] = *(const float4*)(Ab + tx * 8 + 4);

#pragma unroll
    for (int i = 0; i < 4; i++) {
        int r = r0 + ty * 4 + i;
        const float* xr = Xs + (size_t)r * Dp + tx * 8;
        float4 x0 = *(const float4*)xr;
        float4 x1 = *(const float4*)(xr + 4);
        float c[8];
#pragma unroll
        for (int j = 0; j < 8; j++) c[j] = tanhf(acc[i][j] + abv[j]);
        float4 o0 = make_float4(x0.x * c[0], x0.y * c[1], x0.z * c[2], x0.w * c[3]);
        float4 o1 = make_float4(x1.x * c[4], x1.y * c[5], x1.z * c[6], x1.w * c[7]);
        float* dst = g_Xc + (size_t)r * Dp + tx * 8;
        *(float4*)dst = o0;
        *(float4*)(dst + 4) = o1;
    }
}

// ---------------------------------------------------------------------------
// Inner micro-kernel v2: A natural pairs from smem, B duplicated in REGISTERS.
// acc[j][i] (j = m 0..7, i = n-pair 0..3) = (z[n2i][mj], z[n2i+1][mj])
// smem traffic: 64 B/thread/k (was 96).
// ---------------------------------------------------------------------------
#define INNER_K(Asrow, Bsrow)                                               \
    do {                                                                    \
        const ulonglong2* ap = (const ulonglong2*)&(Asrow)[ty * 8];         \
        ulonglong2 a01 = ap[0], a23 = ap[1];                                \
        unsigned long long av[4] = {a01.x, a01.y, a23.x, a23.y};            \
        const float4* bp = (const float4*)&(Bsrow)[tx * 8];                 \
        float4 b0 = bp[0], b1 = bp[1];                                      \
        float bsc[8] = {b0.x, b0.y, b0.z, b0.w, b1.x, b1.y, b1.z, b1.w};    \
        unsigned long long bd[8];                                           \
        _Pragma("unroll") for (int j = 0; j < 8; j++) bd[j] = dup2(bsc[j]); \
        _Pragma("unroll") for (int j = 0; j < 8; j++)                       \
            _Pragma("unroll") for (int i = 0; i < 4; i++)                   \
                acc[j][i] = fma2(av[i], bd[j], acc[j][i]);                  \
    } while (0)

// ---------------------------------------------------------------------------
// K2 (FFMA2, exact fp32): z = Xc @ Y^T; s out (fp32); P = tf32r(1+e^z) out;
// row/col sums of ROUNDED P. 128x128 tile, K=128 in chunks of 8, double-buffered.
// Both smem tiles natural [8][128]; duplication happens in registers.
// ---------------------------------------------------------------------------
__global__ __launch_bounds__(256, 2) void k_scores(const float* __restrict__ Ys,
                                                   float* __restrict__ out_s) {
    const int tx = threadIdx.x, ty = threadIdx.y;
    const int tid = ty * 16 + tx;
    const int mt = blockIdx.x, nt = blockIdx.y, b = blockIdx.z;

    __shared__ __align__(16) float As[2][8][128];
    __shared__ __align__(16) float Bs[2][8][128];
    __shared__ float scs[128];

    unsigned long long acc[8][4];
#pragma unroll
    for (int j = 0; j < 8; j++)
#pragma unroll
        for (int i = 0; i < 4; i++) acc[j][i] = 0ULL;

    const float* Xc = g_Xc + (size_t)(b * Np + nt * 128) * Dp;
    const float* Yb = Ys + (size_t)(b * Mp + mt * 128) * Dp;
    const int n = tid >> 1, kq = tid & 1;

    if (tid < 128) scs[tid] = 0.f;

    // prologue: chunk 0 (rows kq*4..kq*4+3, column n of each tile)
    {
        float4 va = *(const float4*)(Xc + (size_t)n * Dp + kq * 4);
        float4 vb = *(const float4*)(Yb + (size_t)n * Dp + kq * 4);
        As[0][kq * 4 + 0][n] = va.x;
        As[0][kq * 4 + 1][n] = va.y;
        As[0][kq * 4 + 2][n] = va.z;
        As[0][kq * 4 + 3][n] = va.w;
        Bs[0][kq * 4 + 0][n] = vb.x;
        Bs[0][kq * 4 + 1][n] = vb.y;
        Bs[0][kq * 4 + 2][n] = vb.z;
        Bs[0][kq * 4 + 3][n] = vb.w;
    }
    __syncthreads();

    const int NC = Dp / 8;  // 16
#pragma unroll 2
    for (int c = 0; c < NC; c++) {
        const int cur = c & 1;
        float4 pa, pb;
        const bool has = (c + 1 < NC);
        if (has) {
            pa = *(const float4*)(Xc + (size_t)n * Dp + (c + 1) * 8 + kq * 4);
            pb = *(const float4*)(Yb + (size_t)n * Dp + (c + 1) * 8 + kq * 4);
        }
#pragma unroll
        for (int k = 0; k < 8; k++) INNER_K(As[cur][k], Bs[cur][k]);
        if (has) {
            const int nx = cur ^ 1;
            As[nx][kq * 4 + 0][n] = pa.x;
            As[nx][kq * 4 + 1][n] = pa.y;
            As[nx][kq * 4 + 2][n] = pa.z;
            As[nx][kq * 4 + 3][n] = pa.w;
            Bs[nx][kq * 4 + 0][n] = pb.x;
            Bs[nx][kq * 4 + 1][n] = pb.y;
            Bs[nx][kq * 4 + 2][n] = pb.z;
            Bs[nx][kq * 4 + 3][n] = pb.w;
        }
        __syncthreads();
    }

    // epilogue: s (exact fp32), rounded P, sums of rounded P.
    // n-local row = ty*8 + i; m-local col = tx*8 + j.
    const size_t sbase =
        ((size_t)(b * Np + nt * 128 + ty * 8)) * Mp + mt * 128 + tx * 8;

    float csum[8];
#pragma unroll
    for (int j = 0; j < 8; j++) csum[j] = 0.f;

#pragma unroll
    for (int i = 0; i < 8; i++) {
        float sv[8], pv[8];
        float rs = 0.f;
#pragma unroll
        for (int j = 0; j < 8; j++) {
            float2 zp = up2(acc[j][i >> 1]);
            float z = (i & 1) ? zp.y : zp.x;
            float p = 1.f + __expf(z);
            float pr = tf32r(p);
            sv[j] = __logf(p) - 0.5f;        // softplus(z) - 0.5, exact path
            pv[j] = pr;
            rs += pr;
            csum[j] += pr;
        }
        size_t off = sbase + (size_t)i * Mp;
        *(float4*)(out_s + off) = make_float4(sv[0], sv[1], sv[2], sv[3]);
        *(float4*)(out_s + off + 4) = make_float4(sv[4], sv[5], sv[6], sv[7]);
        *(float4*)(g_P + off) = make_float4(pv[0], pv[1], pv[2], pv[3]);
        *(float4*)(g_P + off + 4) = make_float4(pv[4], pv[5], pv[6], pv[7]);

        // reduce rs across the 16 tx lanes (stays within half-warp)
        rs += __shfl_xor_sync(0xFFFFFFFFu, rs, 1);
        rs += __shfl_xor_sync(0xFFFFFFFFu, rs, 2);
        rs += __shfl_xor_sync(0xFFFFFFFFu, rs, 4);
        rs += __shfl_xor_sync(0xFFFFFFFFu, rs, 8);
        if (tx == 0) atomicAdd(&g_rs[b * Np + nt * 128 + ty * 8 + i], rs);
    }

#pragma unroll
    for (int j = 0; j < 8; j++) atomicAdd(&scs[tx * 8 + j], csum[j]);
    __syncthreads();
    if (tid < 128) atomicAdd(&g_cs[b * Mp + mt * 128 + tid], scs[tid]);
}

// ---------------------------------------------------------------------------
// K3 (wmma tf32, merged; operands pre-rounded -> no cvt in loop):
//  mode 0: attn_x[n][d] = sum_m P[n][m] Yr[m][d] / rs[n]   (A row-major)
//  mode 1: attn_y[m][d] = sum_n P[n][m] Xr[n][d] / cs[m]   (A col-major)
// CTA 128 rows x 128 cols, K=1024 in 32 chunks, 3-stage ring.
// ---------------------------------------------------------------------------
__global__ __launch_bounds__(256, 2) void k_attn(float* __restrict__ out_x,
                                                 float* __restrict__ out_y) {
    extern __shared__ __align__(16) float smf[];
    const uint32_t sb = s2u(smf);
    const int t = threadIdx.x;
    const int w = t >> 5;
    const int rt = blockIdx.x;
    const int b = blockIdx.y >> 1;
    const int mode = blockIdx.y & 1;

    const float* Pb = g_P + (size_t)b * Np * Mp;
    const float* Bsrc = mode ? (g_Xr + (size_t)b * Np * Dp)
                             : (g_Yr + (size_t)b * Mp * Dp);

    const int m0 = (w >> 1) * 32, n0 = (w & 1) * 64;

    FragC acc[2][4];
#pragma unroll
    for (int i = 0; i < 2; i++)
#pragma unroll
        for (int j = 0; j < 4; j++) wmma::fill_fragment(acc[i][j], 0.f);

    auto load_chunk = [&](int c, int f) {
        uint32_t Ad = sb + (uint32_t)(f * BUFSZ) * 4;
        uint32_t Bd = Ad + 4352 * 4;
        if (mode == 0) {
#pragma unroll
            for (int i = 0; i < 4; i++) {
                int id = t + i * 256;
                int m = id >> 3, q = id & 7;
                uint32_t doff =
                    (uint32_t)((((q >> 1) * 128 + m) * 8 + (q & 1) * 4) * 4);
                cpa16(Ad + doff,
                      Pb + (size_t)(rt * 128 + m) * Mp + c * 32 + q * 4);
            }
        } else {
#pragma unroll
            for (int i = 0; i < 4; i++) {
                int id = t + i * 256;
                int kr = id >> 5, dq = id & 31;
                cpa16(Ad + (uint32_t)((kr * 132 + dq * 4) * 4),
                      Pb + (size_t)(c * 32 + kr) * Mp + rt * 128 + dq * 4);
            }
        }
#pragma unroll
        for (int i = 0; i < 4; i++) {
            int id = t + i * 256;
            int kr = id >> 5, dq = id & 31;
            cpa16(Bd + (uint32_t)((kr * 132 + dq * 4) * 4),
                  Bsrc + (size_t)(c * 32 + kr) * Dp + dq * 4);
        }
        CP_COMMIT();
    };

    load_chunk(0, 0);
    load_chunk(1, 1);
    const int NC = 32;
    for (int c = 0; c < NC; c++) {
        if (c + 1 < NC) CP_WAIT1(); else CP_WAIT0();
        __syncthreads();
        if (c + 2 < NC) load_chunk(c + 2, (c + 2) % 3);
        const float* As_ = smf + (c % 3) * BUFSZ;
        const float* Bs_ = As_ + 4352;
        if (mode == 0) {
#pragma unroll
            for (int s = 0; s < 4; s++) {
                FragAR af[2];
                FragBR bf[4];
#pragma unroll
                for (int i = 0; i < 2; i++)
                    wmma::load_matrix_sync(af[i], As_ + s * 1024 + (m0 + i * 16) * 8, 8);
#pragma unroll
                for (int j = 0; j < 4; j++)
                    wmma::load_matrix_sync(bf[j], Bs_ + s * 8 * 132 + n0 + j * 16, 132);
#pragma unroll
                for (int i = 0; i < 2; i++)
#pragma unroll
                    for (int j = 0; j < 4; j++)
                        wmma::mma_sync(acc[i][j], af[i], bf[j], acc[i][j]);
            }
        } else {
#pragma unroll
            for (int s = 0; s < 4; s++) {
                FragAC af[2];
                FragBR bf[4];
#pragma unroll
                for (int i = 0; i < 2; i++)
                    wmma::load_matrix_sync(af[i], As_ + s * 8 * 132 + m0 + i * 16, 132);
#pragma unroll
                for (int j = 0; j < 4; j++)
                    wmma::load_matrix_sync(bf[j], Bs_ + s * 8 * 132 + n0 + j * 16, 132);
#pragma unroll
                for (int i = 0; i < 2; i++)
#pragma unroll
                    for (int j = 0; j < 4; j++)
                        wmma::mma_sync(acc[i][j], af[i], bf[j], acc[i][j]);
            }
        }
    }
    __syncthreads();

    // stash, then normalized coalesced write-out
#pragma unroll
    for (int i = 0; i < 2; i++)
#pragma unroll
        for (int j = 0; j < 4; j++)
            wmma::store_matrix_sync(smf + (m0 + i * 16) * 132 + (n0 + j * 16),
                                    acc[i][j], 132, wmma::mem_row_major);
    __syncthreads();

    {
        const int r = t >> 1, h = t & 1;
        const float inv =
            1.f / (mode ? g_cs[b * Mp + rt * 128 + r]
                        : g_rs[b * Np + rt * 128 + r]);
        const float* rowp = smf + r * 132 + h * 64;
        float* outp = (mode ? out_y : out_x) +
                      (size_t)(b * 1024 + rt * 128 + r) * Dp + h * 64;
#pragma unroll
        for (int j = 0; j < 16; j++) {
            float4 v = *(const float4*)(rowp + j * 4);
            *(float4*)(outp + j * 4) =
                make_float4(v.x * inv, v.y * inv, v.z * inv, v.w * inv);
        }
    }
}

// ---------------------------------------------------------------------------
extern "C" void kernel_launch(void* const* d_in, const int* in_sizes, int n_in,
                              void* d_out, int out_size) {
    const float* Xs = (const float*)d_in[0];
    const float* Ys = (const float*)d_in[1];
    const float* W  = (const float*)d_in[2];
    const float* Aw = (const float*)d_in[3];
    const float* Ab = (const float*)d_in[4];

    float* out = (float*)d_out;
    float* out_x = out;                               // [B,N,D]
    float* out_y = out_x + (size_t)Bp * Np * Dp;      // [B,M,D]
    float* out_s = out_y + (size_t)Bp * Mp * Dp;      // [B,N,M]

    cudaFuncSetAttribute(k_attn, cudaFuncAttributeMaxDynamicSharedMemorySize,
                         SMEM_DYN);

    k_zero<<<128, 256>>>();
    k_prep<<<4096, 256>>>(Xs, Ys);
    k_coeff<<<(Bp * Np) / 64, dim3(16, 16)>>>(W, Aw, Ab, Xs);
    k_scores<<<dim3(8, 8, 32), dim3(16, 16)>>>(Ys, out_s);
    k_attn<<<dim3(8, 64), 256, SMEM_DYN>>>(out_x, out_y);
}

// round 10
// speedup vs baseline: 1.1996x; 1.1996x over previous
#include <cuda_runtime.h>
#include <mma.h>
#include <cstdint>

using namespace nvcuda;

#define Bp 32
#define Np 1024
#define Mp 1024
#define Dp 128

// Scratch (device globals; allocation is forbidden everywhere)
__device__ float g_Xc[Bp * Np * Dp];            // X * tanh(W@A^T+b)  [b][n][d] (fp32)
__device__ float g_Xr[Bp * Np * Dp];            // tf32-rounded Xs
__device__ float g_Yr[Bp * Mp * Dp];            // tf32-rounded Ys
__device__ float g_P[(size_t)Bp * Np * Mp];     // P = tf32r(1+e^z)   [b][n][m]
__device__ float g_rs[Bp * Np];                 // row sums of rounded P
__device__ float g_cs[Bp * Mp];                 // col sums of rounded P

// ---------------------------------------------------------------------------
__device__ __forceinline__ uint32_t s2u(const void* p) {
    uint32_t a;
    asm("{ .reg .u64 t; cvta.to.shared.u64 t, %1; cvt.u32.u64 %0, t; }"
        : "=r"(a) : "l"(p));
    return a;
}
__device__ __forceinline__ void cpa16(uint32_t d, const void* s) {
    asm volatile("cp.async.cg.shared.global [%0], [%1], 16;"
                 :: "r"(d), "l"(s) : "memory");
}
#define CP_COMMIT() asm volatile("cp.async.commit_group;" ::: "memory")
#define CP_WAIT1()  asm volatile("cp.async.wait_group 1;" ::: "memory")
#define CP_WAIT0()  asm volatile("cp.async.wait_group 0;" ::: "memory")

__device__ __forceinline__ float tf32r(float x) {
    return wmma::__float_to_tf32(x);
}
__device__ __forceinline__ unsigned long long fma2(unsigned long long a,
                                                   unsigned long long b,
                                                   unsigned long long c) {
    unsigned long long d;
    asm("fma.rn.f32x2 %0, %1, %2, %3;" : "=l"(d) : "l"(a), "l"(b), "l"(c));
    return d;
}
__device__ __forceinline__ float2 up2(unsigned long long u) {
    float2 f;
    asm("mov.b64 {%0, %1}, %2;" : "=f"(f.x), "=f"(f.y) : "l"(u));
    return f;
}

// wmma ring: stage f at f*BUFSZ floats; A @ +0, B @ +4352
#define BUFSZ 8704
#define SMEM_DYN (3 * BUFSZ * 4)   // 104448 bytes

typedef wmma::fragment<wmma::matrix_a, 16, 16, 8, wmma::precision::tf32,
                       wmma::row_major> FragAR;
typedef wmma::fragment<wmma::matrix_a, 16, 16, 8, wmma::precision::tf32,
                       wmma::col_major> FragAC;
typedef wmma::fragment<wmma::matrix_b, 16, 16, 8, wmma::precision::tf32,
                       wmma::row_major> FragBR;
typedef wmma::fragment<wmma::matrix_b, 16, 16, 8, wmma::precision::tf32,
                       wmma::col_major> FragBC;
typedef wmma::fragment<wmma::accumulator, 16, 16, 8, float> FragC;

template <class F>
__device__ __forceinline__ void split2(F& hi, F& lo, const F& a) {
#pragma unroll
    for (int e = 0; e < a.num_elements; e++) {
        float h = wmma::__float_to_tf32(a.x[e]);
        hi.x[e] = h;
        lo.x[e] = wmma::__float_to_tf32(a.x[e] - h);
    }
}

// ---------------------------------------------------------------------------
__global__ void k_zero() {
    int i = blockIdx.x * 256 + threadIdx.x;
    g_rs[i] = 0.f;
    g_cs[i] = 0.f;
}

// tf32-rounded copies of Xs and Ys. 4,194,304 elems / (256*4) = 4096 blocks.
__global__ void k_prep(const float* __restrict__ Xs, const float* __restrict__ Ys) {
    size_t i = ((size_t)blockIdx.x * 256 + threadIdx.x) * 4;
    float4 x = *(const float4*)(Xs + i);
    float4 y = *(const float4*)(Ys + i);
    *(float4*)(g_Xr + i) =
        make_float4(tf32r(x.x), tf32r(x.y), tf32r(x.z), tf32r(x.w));
    *(float4*)(g_Yr + i) =
        make_float4(tf32r(y.x), tf32r(y.y), tf32r(y.z), tf32r(y.w));
}

// ---------------------------------------------------------------------------
// K1: Xc[r][e] = Xs[r][e] * tanh( sum_d W[r][d]*Aw[e][d] + Ab[e] )  (verified)
// ---------------------------------------------------------------------------
__global__ __launch_bounds__(256) void k_coeff(const float* __restrict__ W,
                                               const float* __restrict__ Aw,
                                               const float* __restrict__ Ab,
                                               const float* __restrict__ Xs) {
    const int tx = threadIdx.x, ty = threadIdx.y;
    const int tid = ty * 16 + tx;
    const int r0 = blockIdx.x * 64;

    __shared__ __align__(16) float Ws[64][32];
    __shared__ __align__(16) float Awt[32][132];

    float acc[4][8];
#pragma unroll
    for (int i = 0; i < 4; i++)
#pragma unroll
        for (int j = 0; j < 8; j++) acc[i][j] = 0.f;

    for (int k0 = 0; k0 < Dp; k0 += 32) {
#pragma unroll
        for (int it = 0; it < 2; it++) {
            int id = tid + it * 256;
            int r = id >> 3, q = id & 7;
            *(float4*)&Ws[r][q * 4] =
                *(const float4*)(W + (size_t)(r0 + r) * Dp + k0 + q * 4);
        }
#pragma unroll
        for (int it = 0; it < 4; it++) {
            int id = tid + it * 256;
            int e = id >> 3, q = id & 7;
            float4 v = *(const float4*)(Aw + (size_t)e * Dp + k0 + q * 4);
            Awt[q * 4 + 0][e] = v.x;
            Awt[q * 4 + 1][e] = v.y;
            Awt[q * 4 + 2][e] = v.z;
            Awt[q * 4 + 3][e] = v.w;
        }
        __syncthreads();
#pragma unroll
        for (int k = 0; k < 32; k++) {
            float w0 = Ws[ty * 4 + 0][k];
            float w1 = Ws[ty * 4 + 1][k];
            float w2 = Ws[ty * 4 + 2][k];
            float w3 = Ws[ty * 4 + 3][k];
            float4 a0 = *(const float4*)&Awt[k][tx * 8];
            float4 a1 = *(const float4*)&Awt[k][tx * 8 + 4];
            float av[8] = {a0.x, a0.y, a0.z, a0.w, a1.x, a1.y, a1.z, a1.w};
#pragma unroll
            for (int j = 0; j < 8; j++) {
                acc[0][j] = fmaf(w0, av[j], acc[0][j]);
                acc[1][j] = fmaf(w1, av[j], acc[1][j]);
                acc[2][j] = fmaf(w2, av[j], acc[2][j]);
                acc[3][j] = fmaf(w3, av[j], acc[3][j]);
            }
        }
        __syncthreads();
    }

    float abv[8];
    *(float4*)&abv[0] = *(const float4*)(Ab + tx * 8);
    *(float4*)&abv[4] = *(const float4*)(Ab + tx * 8 + 4);

#pragma unroll
    for (int i = 0; i < 4; i++) {
        int r = r0 + ty * 4 + i;
        const float* xr = Xs + (size_t)r * Dp + tx * 8;
        float4 x0 = *(const float4*)xr;
        float4 x1 = *(const float4*)(xr + 4);
        float c[8];
#pragma unroll
        for (int j = 0; j < 8; j++) c[j] = tanhf(acc[i][j] + abv[j]);
        float4 o0 = make_float4(x0.x * c[0], x0.y * c[1], x0.z * c[2], x0.w * c[3]);
        float4 o1 = make_float4(x1.x * c[4], x1.y * c[5], x1.z * c[6], x1.w * c[7]);
        float* dst = g_Xc + (size_t)r * Dp + tx * 8;
        *(float4*)dst = o0;
        *(float4*)(dst + 4) = o1;
    }
}

// FFMA2 inner: duplicated-pair A rows (256 wide), plain B rows (128 wide). R2/R8 proven.
#define INNER_K(As2row, Bsrow)                                              \
    do {                                                                    \
        const ulonglong2* ap = (const ulonglong2*)&(As2row)[ty * 16];       \
        ulonglong2 a01 = ap[0], a23 = ap[1], a45 = ap[2], a67 = ap[3];      \
        const ulonglong2* bp = (const ulonglong2*)&(Bsrow)[tx * 8];         \
        ulonglong2 b01 = bp[0], b23 = bp[1];                                \
        unsigned long long av[8] = {a01.x, a01.y, a23.x, a23.y,             \
                                    a45.x, a45.y, a67.x, a67.y};            \
        unsigned long long bv[4] = {b01.x, b01.y, b23.x, b23.y};            \
        _Pragma("unroll") for (int i = 0; i < 8; i++)                       \
            _Pragma("unroll") for (int j = 0; j < 4; j++)                   \
                acc[i][j] = fma2(av[i], bv[j], acc[i][j]);                  \
    } while (0)

// ---------------------------------------------------------------------------
// K2 hybrid: z = Xc @ Y^T; s out; P = tf32r(1+e^z) out; sums of rounded P.
// Tile (nt,mt): 36/64 tiles -> FFMA2 exact path (R8); 28/64 -> wmma 3-pass (R7).
// ---------------------------------------------------------------------------
__global__ __launch_bounds__(256, 2) void k_scores(const float* __restrict__ Ys,
                                                   float* __restrict__ out_s) {
    extern __shared__ __align__(16) float smf[];
    const uint32_t sb = s2u(smf);
    const int t = threadIdx.x;
    const int mt = blockIdx.x, nt = blockIdx.y, b = blockIdx.z;
    const int id = nt * 8 + mt;

    const float* Ar = g_Xc + (size_t)(b * Np + nt * 128) * Dp;
    const float* Br = Ys + (size_t)(b * Mp + mt * 128) * Dp;

    if ((id & 15) < 9) {
        // ================= FFMA2 exact path (R8, measured 285us full-grid) ==
        const int tx = t & 15, ty = t >> 4;
        const int tid = t;
        float (*As2)[8][256] = (float(*)[8][256])smf;             // 4096 fl
        float (*Bs)[8][128] = (float(*)[8][128])(smf + 4096);     // 2048 fl
        float* scs = smf + 6144;                                  // 128 fl

        unsigned long long acc[8][4];
#pragma unroll
        for (int i = 0; i < 8; i++)
#pragma unroll
            for (int j = 0; j < 4; j++) acc[i][j] = 0ULL;

        const int n = tid >> 1, kq = tid & 1;
        if (tid < 128) scs[tid] = 0.f;

        {
            float4 va = *(const float4*)(Ar + (size_t)n * Dp + kq * 4);
            float4 vb = *(const float4*)(Br + (size_t)n * Dp + kq * 4);
            ((float2*)&As2[0][kq * 4 + 0][0])[n] = make_float2(va.x, va.x);
            ((float2*)&As2[0][kq * 4 + 1][0])[n] = make_float2(va.y, va.y);
            ((float2*)&As2[0][kq * 4 + 2][0])[n] = make_float2(va.z, va.z);
            ((float2*)&As2[0][kq * 4 + 3][0])[n] = make_float2(va.w, va.w);
            Bs[0][kq * 4 + 0][n] = vb.x;
            Bs[0][kq * 4 + 1][n] = vb.y;
            Bs[0][kq * 4 + 2][n] = vb.z;
            Bs[0][kq * 4 + 3][n] = vb.w;
        }
        __syncthreads();

        const int NC = Dp / 8;
#pragma unroll 2
        for (int c = 0; c < NC; c++) {
            const int cur = c & 1;
            float4 pa, pb;
            const bool has = (c + 1 < NC);
            if (has) {
                pa = *(const float4*)(Ar + (size_t)n * Dp + (c + 1) * 8 + kq * 4);
                pb = *(const float4*)(Br + (size_t)n * Dp + (c + 1) * 8 + kq * 4);
            }
#pragma unroll
            for (int k = 0; k < 8; k++) INNER_K(As2[cur][k], Bs[cur][k]);
            if (has) {
                const int nx = cur ^ 1;
                ((float2*)&As2[nx][kq * 4 + 0][0])[n] = make_float2(pa.x, pa.x);
                ((float2*)&As2[nx][kq * 4 + 1][0])[n] = make_float2(pa.y, pa.y);
                ((float2*)&As2[nx][kq * 4 + 2][0])[n] = make_float2(pa.z, pa.z);
                ((float2*)&As2[nx][kq * 4 + 3][0])[n] = make_float2(pa.w, pa.w);
                Bs[nx][kq * 4 + 0][n] = pb.x;
                Bs[nx][kq * 4 + 1][n] = pb.y;
                Bs[nx][kq * 4 + 2][n] = pb.z;
                Bs[nx][kq * 4 + 3][n] = pb.w;
            }
            __syncthreads();
        }

        const size_t sbase =
            ((size_t)(b * Np + nt * 128 + ty * 8)) * Mp + mt * 128 + tx * 8;

        float csum[8];
#pragma unroll
        for (int j = 0; j < 8; j++) csum[j] = 0.f;

#pragma unroll
        for (int i = 0; i < 8; i++) {
            float sv[8], pv[8];
            float rs = 0.f;
#pragma unroll
            for (int j = 0; j < 4; j++) {
                float2 z = up2(acc[i][j]);
                float p0 = 1.f + __expf(z.x);
                float p1 = 1.f + __expf(z.y);
                float pr0 = tf32r(p0);
                float pr1 = tf32r(p1);
                sv[2 * j] = __logf(p0) - 0.5f;
                sv[2 * j + 1] = __logf(p1) - 0.5f;
                pv[2 * j] = pr0;
                pv[2 * j + 1] = pr1;
                rs += pr0 + pr1;
                csum[2 * j] += pr0;
                csum[2 * j + 1] += pr1;
            }
            size_t off = sbase + (size_t)i * Mp;
            *(float4*)(out_s + off) = make_float4(sv[0], sv[1], sv[2], sv[3]);
            *(float4*)(out_s + off + 4) = make_float4(sv[4], sv[5], sv[6], sv[7]);
            *(float4*)(g_P + off) = make_float4(pv[0], pv[1], pv[2], pv[3]);
            *(float4*)(g_P + off + 4) = make_float4(pv[4], pv[5], pv[6], pv[7]);

            rs += __shfl_xor_sync(0xFFFFFFFFu, rs, 1);
            rs += __shfl_xor_sync(0xFFFFFFFFu, rs, 2);
            rs += __shfl_xor_sync(0xFFFFFFFFu, rs, 4);
            rs += __shfl_xor_sync(0xFFFFFFFFu, rs, 8);
            if (tx == 0) atomicAdd(&g_rs[b * Np + nt * 128 + ty * 8 + i], rs);
        }

#pragma unroll
        for (int j = 0; j < 8; j++) atomicAdd(&scs[tx * 8 + j], csum[j]);
        __syncthreads();
        if (tid < 128) atomicAdd(&g_cs[b * Mp + mt * 128 + tid], scs[tid]);
    } else {
        // ================= wmma 3-pass split path (R7, verified) ============
        const int w = t >> 5;
        const int m0 = (w >> 1) * 32, n0 = (w & 1) * 64;

        FragC acc[2][4];
#pragma unroll
        for (int i = 0; i < 2; i++)
#pragma unroll
            for (int j = 0; j < 4; j++) wmma::fill_fragment(acc[i][j], 0.f);

        auto load_chunk = [&](int c, int f) {
            uint32_t Ad = sb + (uint32_t)(f * BUFSZ) * 4;
            uint32_t Bd = Ad + 4352 * 4;
#pragma unroll
            for (int i = 0; i < 4; i++) {
                int idd = t + i * 256;
                int m = idd >> 3, q = idd & 7;
                uint32_t doff =
                    (uint32_t)((((q >> 1) * 128 + m) * 8 + (q & 1) * 4) * 4);
                cpa16(Ad + doff, Ar + (size_t)m * Dp + c * 32 + q * 4);
                cpa16(Bd + doff, Br + (size_t)m * Dp + c * 32 + q * 4);
            }
            CP_COMMIT();
        };

        load_chunk(0, 0);
        load_chunk(1, 1);
        const int NC = 4;
        for (int c = 0; c < NC; c++) {
            if (c + 1 < NC) CP_WAIT1(); else CP_WAIT0();
            __syncthreads();
            if (c + 2 < NC) load_chunk(c + 2, (c + 2) % 3);
            const float* As_ = smf + (c % 3) * BUFSZ;
            const float* Bs_ = As_ + 4352;
#pragma unroll
            for (int s = 0; s < 4; s++) {
                FragAR ahi[2], alo[2];
#pragma unroll
                for (int i = 0; i < 2; i++) {
                    FragAR af;
                    wmma::load_matrix_sync(af, As_ + s * 1024 + (m0 + i * 16) * 8, 8);
                    split2(ahi[i], alo[i], af);
                }
#pragma unroll
                for (int j = 0; j < 4; j++) {
                    FragBC bf, bhi, blo;
                    wmma::load_matrix_sync(bf, Bs_ + s * 1024 + (n0 + j * 16) * 8, 8);
                    split2(bhi, blo, bf);
#pragma unroll
                    for (int i = 0; i < 2; i++) {
                        wmma::mma_sync(acc[i][j], ahi[i], bhi, acc[i][j]);
                        wmma::mma_sync(acc[i][j], ahi[i], blo, acc[i][j]);
                        wmma::mma_sync(acc[i][j], alo[i], bhi, acc[i][j]);
                    }
                }
            }
            __syncthreads();
        }

#pragma unroll
        for (int i = 0; i < 2; i++)
#pragma unroll
            for (int j = 0; j < 4; j++)
                wmma::store_matrix_sync(smf + (m0 + i * 16) * 132 + (n0 + j * 16),
                                        acc[i][j], 132, wmma::mem_row_major);
        __syncthreads();

        {
            const int r = t >> 1, h = t & 1;
            float* rowp = smf + r * 132 + h * 64;
            float* sp = out_s + (size_t)(b * Np + nt * 128 + r) * Mp + mt * 128 + h * 64;
            float* pp = g_P + (size_t)(b * Np + nt * 128 + r) * Mp + mt * 128 + h * 64;
            float rs = 0.f;
#pragma unroll
            for (int j = 0; j < 16; j++) {
                float4 z = *(float4*)(rowp + j * 4);
                float4 P, Pr, S;
                P.x = 1.f + __expf(z.x); Pr.x = tf32r(P.x); S.x = __logf(P.x) - 0.5f;
                P.y = 1.f + __expf(z.y); Pr.y = tf32r(P.y); S.y = __logf(P.y) - 0.5f;
                P.z = 1.f + __expf(z.z); Pr.z = tf32r(P.z); S.z = __logf(P.z) - 0.5f;
                P.w = 1.f + __expf(z.w); Pr.w = tf32r(P.w); S.w = __logf(P.w) - 0.5f;
                rs += Pr.x + Pr.y + Pr.z + Pr.w;
                *(float4*)(sp + j * 4) = S;
                *(float4*)(pp + j * 4) = Pr;
                *(float4*)(rowp + j * 4) = Pr;
            }
            rs += __shfl_xor_sync(0xFFFFFFFFu, rs, 1);
            if (h == 0) atomicAdd(&g_rs[b * Np + nt * 128 + r], rs);
        }
        __syncthreads();

        if (t < 128) {
            float cs = 0.f;
#pragma unroll 4
            for (int r = 0; r < 128; r++) cs += smf[r * 132 + t];
            atomicAdd(&g_cs[b * Mp + mt * 128 + t], cs);
        }
    }
}

// ---------------------------------------------------------------------------
// K3 hybrid: mode 0: attn_x = P @ Y / rs;  mode 1: attn_y = P^T @ X / cs.
// 6/16 tiles -> FFMA2 (R2 proven, fp32 on g_P/Xs/Ys); rest -> wmma (R8 proven).
// ---------------------------------------------------------------------------
__global__ __launch_bounds__(256, 2) void k_attn(const float* __restrict__ Xs,
                                                 const float* __restrict__ Ys,
                                                 float* __restrict__ out_x,
                                                 float* __restrict__ out_y) {
    extern __shared__ __align__(16) float smf[];
    const uint32_t sb = s2u(smf);
    const int t = threadIdx.x;
    const int rt = blockIdx.x;
    const int b = blockIdx.y >> 1;
    const int mode = blockIdx.y & 1;
    const int id = blockIdx.y * 8 + blockIdx.x;

    const float* Pb = g_P + (size_t)b * Np * Mp;

    if ((id & 15) < 6) {
        // ================= FFMA2 path (R2, measured; full-precision B) ======
        const int tx = t & 15, ty = t >> 4;
        const int tid = t;
        float (*As2)[8][256] = (float(*)[8][256])smf;             // 4096 fl
        float (*Bs)[8][128] = (float(*)[8][128])(smf + 4096);     // 2048 fl

        unsigned long long acc[8][4];
#pragma unroll
        for (int i = 0; i < 8; i++)
#pragma unroll
            for (int j = 0; j < 4; j++) acc[i][j] = 0ULL;

        const float* Bsrc =
            mode ? (Xs + (size_t)b * Np * Dp) : (Ys + (size_t)b * Mp * Dp);
        const int n = tid >> 1, kq = tid & 1;
        const int kr2 = tid >> 5, dq = tid & 31;

        {
            if (mode == 0) {
                float4 va = *(const float4*)(Pb + (size_t)(rt * 128 + n) * Mp + kq * 4);
                ((float2*)&As2[0][kq * 4 + 0][0])[n] = make_float2(va.x, va.x);
                ((float2*)&As2[0][kq * 4 + 1][0])[n] = make_float2(va.y, va.y);
                ((float2*)&As2[0][kq * 4 + 2][0])[n] = make_float2(va.z, va.z);
                ((float2*)&As2[0][kq * 4 + 3][0])[n] = make_float2(va.w, va.w);
            } else {
                float4 va = *(const float4*)(Pb + (size_t)kr2 * Mp + rt * 128 + dq * 4);
                ((float2*)&As2[0][kr2][0])[dq * 4 + 0] = make_float2(va.x, va.x);
                ((float2*)&As2[0][kr2][0])[dq * 4 + 1] = make_float2(va.y, va.y);
                ((float2*)&As2[0][kr2][0])[dq * 4 + 2] = make_float2(va.z, va.z);
                ((float2*)&As2[0][kr2][0])[dq * 4 + 3] = make_float2(va.w, va.w);
            }
            *(float4*)&Bs[0][kr2][dq * 4] =
                *(const float4*)(Bsrc + (size_t)kr2 * Dp + dq * 4);
        }
        __syncthreads();

        const int NC = Mp / 8;  // 128
#pragma unroll 2
        for (int c = 0; c < NC; c++) {
            const int cur = c & 1;
            float4 pa, pb;
            const bool has = (c + 1 < NC);
            if (has) {
                const int k0 = (c + 1) * 8;
                if (mode == 0)
                    pa = *(const float4*)(Pb + (size_t)(rt * 128 + n) * Mp + k0 + kq * 4);
                else
                    pa = *(const float4*)(Pb + (size_t)(k0 + kr2) * Mp + rt * 128 + dq * 4);
                pb = *(const float4*)(Bsrc + (size_t)(k0 + kr2) * Dp + dq * 4);
            }
#pragma unroll
            for (int k = 0; k < 8; k++) INNER_K(As2[cur][k], Bs[cur][k]);
            if (has) {
                const int nx = cur ^ 1;
                if (mode == 0) {
                    ((float2*)&As2[nx][kq * 4 + 0][0])[n] = make_float2(pa.x, pa.x);
                    ((float2*)&As2[nx][kq * 4 + 1][0])[n] = make_float2(pa.y, pa.y);
                    ((float2*)&As2[nx][kq * 4 + 2][0])[n] = make_float2(pa.z, pa.z);
                    ((float2*)&As2[nx][kq * 4 + 3][0])[n] = make_float2(pa.w, pa.w);
                } else {
                    ((float2*)&As2[nx][kr2][0])[dq * 4 + 0] = make_float2(pa.x, pa.x);
                    ((float2*)&As2[nx][kr2][0])[dq * 4 + 1] = make_float2(pa.y, pa.y);
                    ((float2*)&As2[nx][kr2][0])[dq * 4 + 2] = make_float2(pa.z, pa.z);
                    ((float2*)&As2[nx][kr2][0])[dq * 4 + 3] = make_float2(pa.w, pa.w);
                }
                *(float4*)&Bs[nx][kr2][dq * 4] = pb;
            }
            __syncthreads();
        }

        const float* norm =
            mode ? &g_cs[b * Mp + rt * 128] : &g_rs[b * Np + rt * 128];
        float* outp =
            mode ? (out_y + (size_t)b * Mp * Dp) : (out_x + (size_t)b * Np * Dp);

        float inv[8];
#pragma unroll
        for (int i = 0; i < 8; i++) inv[i] = 1.0f / norm[ty * 8 + i];

#pragma unroll
        for (int i = 0; i < 8; i++) {
            float o[8];
#pragma unroll
            for (int j = 0; j < 4; j++) {
                float2 v = up2(acc[i][j]);
                o[2 * j] = v.x * inv[i];
                o[2 * j + 1] = v.y * inv[i];
            }
            size_t off = (size_t)(rt * 128 + ty * 8 + i) * Dp + tx * 8;
            *(float4*)(outp + off) = make_float4(o[0], o[1], o[2], o[3]);
            *(float4*)(outp + off + 4) = make_float4(o[4], o[5], o[6], o[7]);
        }
    } else {
        // ================= wmma path (R8, measured) =========================
        const int w = t >> 5;
        const int m0 = (w >> 1) * 32, n0 = (w & 1) * 64;
        const float* Bsrc = mode ? (g_Xr + (size_t)b * Np * Dp)
                                 : (g_Yr + (size_t)b * Mp * Dp);

        FragC acc[2][4];
#pragma unroll
        for (int i = 0; i < 2; i++)
#pragma unroll
            for (int j = 0; j < 4; j++) wmma::fill_fragment(acc[i][j], 0.f);

        auto load_chunk = [&](int c, int f) {
            uint32_t Ad = sb + (uint32_t)(f * BUFSZ) * 4;
            uint32_t Bd = Ad + 4352 * 4;
            if (mode == 0) {
#pragma unroll
                for (int i = 0; i < 4; i++) {
                    int idd = t + i * 256;
                    int m = idd >> 3, q = idd & 7;
                    uint32_t doff =
                        (uint32_t)((((q >> 1) * 128 + m) * 8 + (q & 1) * 4) * 4);
                    cpa16(Ad + doff,
                          Pb + (size_t)(rt * 128 + m) * Mp + c * 32 + q * 4);
                }
            } else {
#pragma unroll
                for (int i = 0; i < 4; i++) {
                    int idd = t + i * 256;
                    int kr = idd >> 5, dq = idd & 31;
                    cpa16(Ad + (uint32_t)((kr * 132 + dq * 4) * 4),
                          Pb + (size_t)(c * 32 + kr) * Mp + rt * 128 + dq * 4);
                }
            }
#pragma unroll
            for (int i = 0; i < 4; i++) {
                int idd = t + i * 256;
                int kr = idd >> 5, dq = idd & 31;
                cpa16(Bd + (uint32_t)((kr * 132 + dq * 4) * 4),
                      Bsrc + (size_t)(c * 32 + kr) * Dp + dq * 4);
            }
            CP_COMMIT();
        };

        load_chunk(0, 0);
        load_chunk(1, 1);
        const int NC = 32;
        for (int c = 0; c < NC; c++) {
            if (c + 1 < NC) CP_WAIT1(); else CP_WAIT0();
            __syncthreads();
            if (c + 2 < NC) load_chunk(c + 2, (c + 2) % 3);
            const float* As_ = smf + (c % 3) * BUFSZ;
            const float* Bs_ = As_ + 4352;
            if (mode == 0) {
#pragma unroll
                for (int s = 0; s < 4; s++) {
                    FragAR af[2];
                    FragBR bf[4];
#pragma unroll
                    for (int i = 0; i < 2; i++)
                        wmma::load_matrix_sync(af[i], As_ + s * 1024 + (m0 + i * 16) * 8, 8);
#pragma unroll
                    for (int j = 0; j < 4; j++)
                        wmma::load_matrix_sync(bf[j], Bs_ + s * 8 * 132 + n0 + j * 16, 132);
#pragma unroll
                    for (int i = 0; i < 2; i++)
#pragma unroll
                        for (int j = 0; j < 4; j++)
                            wmma::mma_sync(acc[i][j], af[i], bf[j], acc[i][j]);
                }
            } else {
#pragma unroll
                for (int s = 0; s < 4; s++) {
                    FragAC af[2];
                    FragBR bf[4];
#pragma unroll
                    for (int i = 0; i < 2; i++)
                        wmma::load_matrix_sync(af[i], As_ + s * 8 * 132 + m0 + i * 16, 132);
#pragma unroll
                    for (int j = 0; j < 4; j++)
                        wmma::load_matrix_sync(bf[j], Bs_ + s * 8 * 132 + n0 + j * 16, 132);
#pragma unroll
                    for (int i = 0; i < 2; i++)
#pragma unroll
                        for (int j = 0; j < 4; j++)
                            wmma::mma_sync(acc[i][j], af[i], bf[j], acc[i][j]);
                }
            }
        }
        __syncthreads();

#pragma unroll
        for (int i = 0; i < 2; i++)
#pragma unroll
            for (int j = 0; j < 4; j++)
                wmma::store_matrix_sync(smf + (m0 + i * 16) * 132 + (n0 + j * 16),
                                        acc[i][j], 132, wmma::mem_row_major);
        __syncthreads();

        {
            const int r = t >> 1, h = t & 1;
            const float inv =
                1.f / (mode ? g_cs[b * Mp + rt * 128 + r]
                            : g_rs[b * Np + rt * 128 + r]);
            const float* rowp = smf + r * 132 + h * 64;
            float* outp = (mode ? out_y : out_x) +
                          (size_t)(b * 1024 + rt * 128 + r) * Dp + h * 64;
#pragma unroll
            for (int j = 0; j < 16; j++) {
                float4 v = *(const float4*)(rowp + j * 4);
                *(float4*)(outp + j * 4) =
                    make_float4(v.x * inv, v.y * inv, v.z * inv, v.w * inv);
            }
        }
    }
}

// ---------------------------------------------------------------------------
extern "C" void kernel_launch(void* const* d_in, const int* in_sizes, int n_in,
                              void* d_out, int out_size) {
    const float* Xs = (const float*)d_in[0];
    const float* Ys = (const float*)d_in[1];
    const float* W  = (const float*)d_in[2];
    const float* Aw = (const float*)d_in[3];
    const float* Ab = (const float*)d_in[4];

    float* out = (float*)d_out;
    float* out_x = out;                               // [B,N,D]
    float* out_y = out_x + (size_t)Bp * Np * Dp;      // [B,M,D]
    float* out_s = out_y + (size_t)Bp * Mp * Dp;      // [B,N,M]

    cudaFuncSetAttribute(k_scores, cudaFuncAttributeMaxDynamicSharedMemorySize,
                         SMEM_DYN);
    cudaFuncSetAttribute(k_attn, cudaFuncAttributeMaxDynamicSharedMemorySize,
                         SMEM_DYN);

    k_zero<<<128, 256>>>();
    k_prep<<<4096, 256>>>(Xs, Ys);
    k_coeff<<<(Bp * Np) / 64, dim3(16, 16)>>>(W, Aw, Ab, Xs);
    k_scores<<<dim3(8, 8, 32), 256, SMEM_DYN>>>(Ys, out_s);
    k_attn<<<dim3(8, 64), 256, SMEM_DYN>>>(Xs, Ys, out_x, out_y);
}

// round 12
// speedup vs baseline: 1.6565x; 1.3808x over previous
#include <cuda_runtime.h>
#include <mma.h>
#include <cstdint>

using namespace nvcuda;

#define Bp 32
#define Np 1024
#define Mp 1024
#define Dp 128

// Scratch (device globals; allocation is forbidden everywhere)
__device__ float g_Xc[Bp * Np * Dp];            // X * tanh(W@A^T+b)  [b][n][d] (fp32)
__device__ float g_Xr[Bp * Np * Dp];            // tf32-rounded Xs
__device__ float g_Yr[Bp * Mp * Dp];            // tf32-rounded Ys
__device__ float g_P[(size_t)Bp * Np * Mp];     // P = tf32r(1+e^z)   [b][n][m]
__device__ float g_rs[Bp * Np];                 // row sums of rounded P
__device__ float g_cs[Bp * Mp];                 // col sums of rounded P

// ---------------------------------------------------------------------------
__device__ __forceinline__ uint32_t s2u(const void* p) {
    uint32_t a;
    asm("{ .reg .u64 t; cvta.to.shared.u64 t, %1; cvt.u32.u64 %0, t; }"
        : "=r"(a) : "l"(p));
    return a;
}
__device__ __forceinline__ void cpa16(uint32_t d, const void* s) {
    asm volatile("cp.async.cg.shared.global [%0], [%1], 16;"
                 :: "r"(d), "l"(s) : "memory");
}
#define CP_COMMIT() asm volatile("cp.async.commit_group;" ::: "memory")
#define CP_WAIT1()  asm volatile("cp.async.wait_group 1;" ::: "memory")
#define CP_WAIT0()  asm volatile("cp.async.wait_group 0;" ::: "memory")

__device__ __forceinline__ float tf32r(float x) {
    return wmma::__float_to_tf32(x);
}
__device__ __forceinline__ unsigned long long fma2(unsigned long long a,
                                                   unsigned long long b,
                                                   unsigned long long c) {
    unsigned long long d;
    asm("fma.rn.f32x2 %0, %1, %2, %3;" : "=l"(d) : "l"(a), "l"(b), "l"(c));
    return d;
}
__device__ __forceinline__ float2 up2(unsigned long long u) {
    float2 f;
    asm("mov.b64 {%0, %1}, %2;" : "=f"(f.x), "=f"(f.y) : "l"(u));
    return f;
}

typedef wmma::fragment<wmma::matrix_a, 16, 16, 8, wmma::precision::tf32,
                       wmma::row_major> FragAR;
typedef wmma::fragment<wmma::matrix_a, 16, 16, 8, wmma::precision::tf32,
                       wmma::col_major> FragAC;
typedef wmma::fragment<wmma::matrix_b, 16, 16, 8, wmma::precision::tf32,
                       wmma::row_major> FragBR;
typedef wmma::fragment<wmma::accumulator, 16, 16, 8, float> FragC;

// attn smem: 3-stage ring. Stage = A(128x20 = 2560 fl) + B(16x68 = 1088 fl)
#define STAGE_FL 3648
#define AB_OFF   2560
#define SMEM_ATTN (3 * STAGE_FL * 4)   // 43776 B -> 4 CTAs/SM

// ---------------------------------------------------------------------------
__global__ void k_zero() {
    int i = blockIdx.x * 256 + threadIdx.x;
    g_rs[i] = 0.f;
    g_cs[i] = 0.f;
}

// tf32-rounded copies of Xs and Ys. 4,194,304 elems / (256*4) = 4096 blocks.
__global__ void k_prep(const float* __restrict__ Xs, const float* __restrict__ Ys) {
    size_t i = ((size_t)blockIdx.x * 256 + threadIdx.x) * 4;
    float4 x = *(const float4*)(Xs + i);
    float4 y = *(const float4*)(Ys + i);
    *(float4*)(g_Xr + i) =
        make_float4(tf32r(x.x), tf32r(x.y), tf32r(x.z), tf32r(x.w));
    *(float4*)(g_Yr + i) =
        make_float4(tf32r(y.x), tf32r(y.y), tf32r(y.z), tf32r(y.w));
}

// ---------------------------------------------------------------------------
// K1: Xc[r][e] = Xs[r][e] * tanh( sum_d W[r][d]*Aw[e][d] + Ab[e] )  (verified)
// ---------------------------------------------------------------------------
__global__ __launch_bounds__(256) void k_coeff(const float* __restrict__ W,
                                               const float* __restrict__ Aw,
                                               const float* __restrict__ Ab,
                                               const float* __restrict__ Xs) {
    const int tx = threadIdx.x, ty = threadIdx.y;
    const int tid = ty * 16 + tx;
    const int r0 = blockIdx.x * 64;

    __shared__ __align__(16) float Ws[64][32];
    __shared__ __align__(16) float Awt[32][132];

    float acc[4][8];
#pragma unroll
    for (int i = 0; i < 4; i++)
#pragma unroll
        for (int j = 0; j < 8; j++) acc[i][j] = 0.f;

    for (int k0 = 0; k0 < Dp; k0 += 32) {
#pragma unroll
        for (int it = 0; it < 2; it++) {
            int id = tid + it * 256;
            int r = id >> 3, q = id & 7;
            *(float4*)&Ws[r][q * 4] =
                *(const float4*)(W + (size_t)(r0 + r) * Dp + k0 + q * 4);
        }
#pragma unroll
        for (int it = 0; it < 4; it++) {
            int id = tid + it * 256;
            int e = id >> 3, q = id & 7;
            float4 v = *(const float4*)(Aw + (size_t)e * Dp + k0 + q * 4);
            Awt[q * 4 + 0][e] = v.x;
            Awt[q * 4 + 1][e] = v.y;
            Awt[q * 4 + 2][e] = v.z;
            Awt[q * 4 + 3][e] = v.w;
        }
        __syncthreads();
#pragma unroll
        for (int k = 0; k < 32; k++) {
            float w0 = Ws[ty * 4 + 0][k];
            float w1 = Ws[ty * 4 + 1][k];
            float w2 = Ws[ty * 4 + 2][k];
            float w3 = Ws[ty * 4 + 3][k];
            float4 a0 = *(const float4*)&Awt[k][tx * 8];
            float4 a1 = *(const float4*)&Awt[k][tx * 8 + 4];
            float av[8] = {a0.x, a0.y, a0.z, a0.w, a1.x, a1.y, a1.z, a1.w};
#pragma unroll
            for (int j = 0; j < 8; j++) {
                acc[0][j] = fmaf(w0, av[j], acc[0][j]);
                acc[1][j] = fmaf(w1, av[j], acc[1][j]);
                acc[2][j] = fmaf(w2, av[j], acc[2][j]);
                acc[3][j] = fmaf(w3, av[j], acc[3][j]);
            }
        }
        __syncthreads();
    }

    float abv[8];
    *(float4*)&abv[0] = *(const float4*)(Ab + tx * 8);
    *(float4*)&abv[4] = *(const float4*)(Ab + tx * 8 + 4);

#pragma unroll
    for (int i = 0; i < 4; i++) {
        int r = r0 + ty * 4 + i;
        const float* xr = Xs + (size_t)r * Dp + tx * 8;
        float4 x0 = *(const float4*)xr;
        float4 x1 = *(const float4*)(xr + 4);
        float c[8];
#pragma unroll
        for (int j = 0; j < 8; j++) c[j] = tanhf(acc[i][j] + abv[j]);
        float4 o0 = make_float4(x0.x * c[0], x0.y * c[1], x0.z * c[2], x0.w * c[3]);
        float4 o1 = make_float4(x1.x * c[4], x1.y * c[5], x1.z * c[6], x1.w * c[7]);
        float* dst = g_Xc + (size_t)r * Dp + tx * 8;
        *(float4*)dst = o0;
        *(float4*)(dst + 4) = o1;
    }
}

// FFMA2 inner: duplicated-pair A rows (256 wide), plain B rows (128 wide). Proven.
#define INNER_K(As2row, Bsrow)                                              \
    do {                                                                    \
        const ulonglong2* ap = (const ulonglong2*)&(As2row)[ty * 16];       \
        ulonglong2 a01 = ap[0], a23 = ap[1], a45 = ap[2], a67 = ap[3];      \
        const ulonglong2* bp = (const ulonglong2*)&(Bsrow)[tx * 8];         \
        ulonglong2 b01 = bp[0], b23 = bp[1];                                \
        unsigned long long av[8] = {a01.x, a01.y, a23.x, a23.y,             \
                                    a45.x, a45.y, a67.x, a67.y};            \
        unsigned long long bv[4] = {b01.x, b01.y, b23.x, b23.y};            \
        _Pragma("unroll") for (int i = 0; i < 8; i++)                       \
            _Pragma("unroll") for (int j = 0; j < 4; j++)                   \
                acc[i][j] = fma2(av[i], bv[j], acc[i][j]);                  \
    } while (0)

// ---------------------------------------------------------------------------
// K2 (FFMA2, exact fp32 — R8, measured 285us): z = Xc @ Y^T; s out (fp32);
// P = tf32r(1+e^z) out; row/col sums of ROUNDED P.
// ---------------------------------------------------------------------------
__global__ __launch_bounds__(256, 2) void k_scores(const float* __restrict__ Ys,
                                                   float* __restrict__ out_s) {
    const int tx = threadIdx.x, ty = threadIdx.y;
    const int tid = ty * 16 + tx;
    const int mt = blockIdx.x, nt = blockIdx.y, b = blockIdx.z;

    __shared__ __align__(16) float As2[2][8][256];
    __shared__ __align__(16) float Bs[2][8][128];
    __shared__ float scs[128];

    unsigned long long acc[8][4];
#pragma unroll
    for (int i = 0; i < 8; i++)
#pragma unroll
        for (int j = 0; j < 4; j++) acc[i][j] = 0ULL;

    const float* Xc = g_Xc + (size_t)(b * Np + nt * 128) * Dp;
    const float* Yb = Ys + (size_t)(b * Mp + mt * 128) * Dp;
    const int n = tid >> 1, kq = tid & 1;

    if (tid < 128) scs[tid] = 0.f;

    {
        float4 va = *(const float4*)(Xc + (size_t)n * Dp + kq * 4);
        float4 vb = *(const float4*)(Yb + (size_t)n * Dp + kq * 4);
        ((float2*)&As2[0][kq * 4 + 0][0])[n] = make_float2(va.x, va.x);
        ((float2*)&As2[0][kq * 4 + 1][0])[n] = make_float2(va.y, va.y);
        ((float2*)&As2[0][kq * 4 + 2][0])[n] = make_float2(va.z, va.z);
        ((float2*)&As2[0][kq * 4 + 3][0])[n] = make_float2(va.w, va.w);
        Bs[0][kq * 4 + 0][n] = vb.x;
        Bs[0][kq * 4 + 1][n] = vb.y;
        Bs[0][kq * 4 + 2][n] = vb.z;
        Bs[0][kq * 4 + 3][n] = vb.w;
    }
    __syncthreads();

    const int NC = Dp / 8;  // 16
#pragma unroll 2
    for (int c = 0; c < NC; c++) {
        const int cur = c & 1;
        float4 pa, pb;
        const bool has = (c + 1 < NC);
        if (has) {
            pa = *(const float4*)(Xc + (size_t)n * Dp + (c + 1) * 8 + kq * 4);
            pb = *(const float4*)(Yb + (size_t)n * Dp + (c + 1) * 8 + kq * 4);
        }
#pragma unroll
        for (int k = 0; k < 8; k++) INNER_K(As2[cur][k], Bs[cur][k]);
        if (has) {
            const int nx = cur ^ 1;
            ((float2*)&As2[nx][kq * 4 + 0][0])[n] = make_float2(pa.x, pa.x);
            ((float2*)&As2[nx][kq * 4 + 1][0])[n] = make_float2(pa.y, pa.y);
            ((float2*)&As2[nx][kq * 4 + 2][0])[n] = make_float2(pa.z, pa.z);
            ((float2*)&As2[nx][kq * 4 + 3][0])[n] = make_float2(pa.w, pa.w);
            Bs[nx][kq * 4 + 0][n] = pb.x;
            Bs[nx][kq * 4 + 1][n] = pb.y;
            Bs[nx][kq * 4 + 2][n] = pb.z;
            Bs[nx][kq * 4 + 3][n] = pb.w;
        }
        __syncthreads();
    }

    const size_t sbase =
        ((size_t)(b * Np + nt * 128 + ty * 8)) * Mp + mt * 128 + tx * 8;

    float csum[8];
#pragma unroll
    for (int j = 0; j < 8; j++) csum[j] = 0.f;

#pragma unroll
    for (int i = 0; i < 8; i++) {
        float sv[8], pv[8];
        float rs = 0.f;
#pragma unroll
        for (int j = 0; j < 4; j++) {
            float2 z = up2(acc[i][j]);
            float p0 = 1.f + __expf(z.x);
            float p1 = 1.f + __expf(z.y);
            float pr0 = tf32r(p0);
            float pr1 = tf32r(p1);
            sv[2 * j] = __logf(p0) - 0.5f;
            sv[2 * j + 1] = __logf(p1) - 0.5f;
            pv[2 * j] = pr0;
            pv[2 * j + 1] = pr1;
            rs += pr0 + pr1;
            csum[2 * j] += pr0;
            csum[2 * j + 1] += pr1;
        }
        size_t off = sbase + (size_t)i * Mp;
        *(float4*)(out_s + off) = make_float4(sv[0], sv[1], sv[2], sv[3]);
        *(float4*)(out_s + off + 4) = make_float4(sv[4], sv[5], sv[6], sv[7]);
        *(float4*)(g_P + off) = make_float4(pv[0], pv[1], pv[2], pv[3]);
        *(float4*)(g_P + off + 4) = make_float4(pv[4], pv[5], pv[6], pv[7]);

        rs += __shfl_xor_sync(0xFFFFFFFFu, rs, 1);
        rs += __shfl_xor_sync(0xFFFFFFFFu, rs, 2);
        rs += __shfl_xor_sync(0xFFFFFFFFu, rs, 4);
        rs += __shfl_xor_sync(0xFFFFFFFFu, rs, 8);
        if (tx == 0) atomicAdd(&g_rs[b * Np + nt * 128 + ty * 8 + i], rs);
    }

#pragma unroll
    for (int j = 0; j < 8; j++) atomicAdd(&scs[tx * 8 + j], csum[j]);
    __syncthreads();
    if (tid < 128) atomicAdd(&g_cs[b * Mp + mt * 128 + tid], scs[tid]);
}

// ---------------------------------------------------------------------------
// K3 (wmma tf32, latency-restructured):
//  128 threads / CTA (4 warps), CTA tile 128 rows x 64 cols (d half),
//  4 CTAs/SM (16K regs, 43.8KB smem), 3-stage ring, k-chunk 16.
//  mode 0: attn_x[n][d] = sum_m P[n][m] Yr[m][d] / rs[n]   (A row-major, ldm 20)
//  mode 1: attn_y[m][d] = sum_n P[n][m] Xr[n][d] / cs[m]   (A col-major, ldm 132)
// ---------------------------------------------------------------------------
__global__ __launch_bounds__(128, 4) void k_attn(float* __restrict__ out_x,
                                                 float* __restrict__ out_y) {
    extern __shared__ __align__(16) float smf[];
    const uint32_t sb = s2u(smf);
    const int t = threadIdx.x;
    const int w = t >> 5;
    const int rt = blockIdx.x;          // 128-row tile
    const int d0 = blockIdx.y * 64;     // d half
    const int b = blockIdx.z & 31;
    const int mode = blockIdx.z >> 5;

    const float* Pb = g_P + (size_t)b * Np * Mp;
    const float* Bsrc = mode ? (g_Xr + (size_t)b * Np * Dp)
                             : (g_Yr + (size_t)b * Mp * Dp);

    const int m0 = w * 32;              // warp row base (warp tile 32x64)

    FragC acc[2][4];
#pragma unroll
    for (int i = 0; i < 2; i++)
#pragma unroll
        for (int j = 0; j < 4; j++) wmma::fill_fragment(acc[i][j], 0.f);

    // stage layout: A @ +0 (mode0: [128][20]; mode1: [16][132]); B @ +2560 ([16][68])
    auto load_chunk = [&](int c, int f) {
        uint32_t Ad = sb + (uint32_t)(f * STAGE_FL) * 4;
        uint32_t Bd = Ad + AB_OFF * 4;
        if (mode == 0) {
#pragma unroll
            for (int o = 0; o < 4; o++) {
                int idx = t + o * 128;
                int row = idx >> 2, q = idx & 3;
                cpa16(Ad + (uint32_t)((row * 20 + q * 4) * 4),
                      Pb + (size_t)(rt * 128 + row) * Mp + c * 16 + q * 4);
            }
        } else {
#pragma unroll
            for (int o = 0; o < 4; o++) {
                int idx = t + o * 128;
                int kr = idx >> 5, mq = idx & 31;
                cpa16(Ad + (uint32_t)((kr * 132 + mq * 4) * 4),
                      Pb + (size_t)(c * 16 + kr) * Mp + rt * 128 + mq * 4);
            }
        }
#pragma unroll
        for (int o = 0; o < 2; o++) {
            int idx = t + o * 128;
            int kr = idx >> 4, dq = idx & 15;
            cpa16(Bd + (uint32_t)((kr * 68 + dq * 4) * 4),
                  Bsrc + (size_t)(c * 16 + kr) * Dp + d0 + dq * 4);
        }
        CP_COMMIT();
    };

    load_chunk(0, 0);
    load_chunk(1, 1);
    const int NC = 64;   // K = 1024 in chunks of 16
    for (int c = 0; c < NC; c++) {
        if (c + 1 < NC) CP_WAIT1(); else CP_WAIT0();
        __syncthreads();
        if (c + 2 < NC) load_chunk(c + 2, (c + 2) % 3);
        const float* As_ = smf + (c % 3) * STAGE_FL;
        const float* Bs_ = As_ + AB_OFF;
        if (mode == 0) {
#pragma unroll
            for (int s = 0; s < 2; s++) {
                FragAR af[2];
                FragBR bf[4];
#pragma unroll
                for (int i = 0; i < 2; i++)
                    wmma::load_matrix_sync(af[i], As_ + (m0 + i * 16) * 20 + s * 8, 20);
#pragma unroll
                for (int j = 0; j < 4; j++)
                    wmma::load_matrix_sync(bf[j], Bs_ + (s * 8) * 68 + j * 16, 68);
#pragma unroll
                for (int i = 0; i < 2; i++)
#pragma unroll
                    for (int j = 0; j < 4; j++)
                        wmma::mma_sync(acc[i][j], af[i], bf[j], acc[i][j]);
            }
        } else {
#pragma unroll
            for (int s = 0; s < 2; s++) {
                FragAC af[2];
                FragBR bf[4];
#pragma unroll
                for (int i = 0; i < 2; i++)
                    wmma::load_matrix_sync(af[i], As_ + (s * 8) * 132 + m0 + i * 16, 132);
#pragma unroll
                for (int j = 0; j < 4; j++)
                    wmma::load_matrix_sync(bf[j], Bs_ + (s * 8) * 68 + j * 16, 68);
#pragma unroll
                for (int i = 0; i < 2; i++)
#pragma unroll
                    for (int j = 0; j < 4; j++)
                        wmma::mma_sync(acc[i][j], af[i], bf[j], acc[i][j]);
            }
        }
    }
    __syncthreads();

    // stash to smem [128][68], then normalized coalesced write-out
#pragma unroll
    for (int i = 0; i < 2; i++)
#pragma unroll
        for (int j = 0; j < 4; j++)
            wmma::store_matrix_sync(smf + (m0 + i * 16) * 68 + j * 16,
                                    acc[i][j], 68, wmma::mem_row_major);
    __syncthreads();

    {
        const int r = t;   // each thread owns one output row (64 cols)
        const float inv =
            1.f / (mode ? g_cs[b * Mp + rt * 128 + r]
                        : g_rs[b * Np + rt * 128 + r]);
        const float* rowp = smf + r * 68;
        float* outp = (mode ? out_y : out_x) +
                      (size_t)(b * 1024 + rt * 128 + r) * Dp + d0;
#pragma unroll
        for (int j = 0; j < 16; j++) {
            float4 v = *(const float4*)(rowp + j * 4);
            *(float4*)(outp + j * 4) =
                make_float4(v.x * inv, v.y * inv, v.z * inv, v.w * inv);
        }
    }
}

// ---------------------------------------------------------------------------
extern "C" void kernel_launch(void* const* d_in, const int* in_sizes, int n_in,
                              void* d_out, int out_size) {
    const float* Xs = (const float*)d_in[0];
    const float* Ys = (const float*)d_in[1];
    const float* W  = (const float*)d_in[2];
    const float* Aw = (const float*)d_in[3];
    const float* Ab = (const float*)d_in[4];

    float* out = (float*)d_out;
    float* out_x = out;                               // [B,N,D]
    float* out_y = out_x + (size_t)Bp * Np * Dp;      // [B,M,D]
    float* out_s = out_y + (size_t)Bp * Mp * Dp;      // [B,N,M]

    cudaFuncSetAttribute(k_attn, cudaFuncAttributeMaxDynamicSharedMemorySize,
                         SMEM_ATTN);

    k_zero<<<128, 256>>>();
    k_prep<<<4096, 256>>>(Xs, Ys);
    k_coeff<<<(Bp * Np) / 64, dim3(16, 16)>>>(W, Aw, Ab, Xs);
    k_scores<<<dim3(8, 8, 32), dim3(16, 16)>>>(Ys, out_s);
    k_attn<<<dim3(8, 2, 64), 128, SMEM_ATTN>>>(out_x, out_y);
}

// round 13
// speedup vs baseline: 1.6671x; 1.0064x over previous
#include <cuda_runtime.h>
#include <mma.h>
#include <cstdint>

using namespace nvcuda;

#define Bp 32
#define Np 1024
#define Mp 1024
#define Dp 128

// Scratch (device globals; allocation is forbidden everywhere)
__device__ float g_Xc[Bp * Np * Dp];            // X * tanh(W@A^T+b)  [b][n][d] (fp32)
__device__ float g_Xr[Bp * Np * Dp];            // tf32-rounded Xs
__device__ float g_Yr[Bp * Mp * Dp];            // tf32-rounded Ys
__device__ float g_P[(size_t)Bp * Np * Mp];     // P = tf32r(1+e^z)   [b][n][m]
__device__ float g_rs[Bp * Np];                 // row sums of rounded P
__device__ float g_cs[Bp * Mp];                 // col sums of rounded P

// ---------------------------------------------------------------------------
__device__ __forceinline__ uint32_t s2u(const void* p) {
    uint32_t a;
    asm("{ .reg .u64 t; cvta.to.shared.u64 t, %1; cvt.u32.u64 %0, t; }"
        : "=r"(a) : "l"(p));
    return a;
}
__device__ __forceinline__ void cpa16(uint32_t d, const void* s) {
    asm volatile("cp.async.cg.shared.global [%0], [%1], 16;"
                 :: "r"(d), "l"(s) : "memory");
}
#define CP_COMMIT() asm volatile("cp.async.commit_group;" ::: "memory")
#define CP_WAIT1()  asm volatile("cp.async.wait_group 1;" ::: "memory")
#define CP_WAIT0()  asm volatile("cp.async.wait_group 0;" ::: "memory")

__device__ __forceinline__ float tf32r(float x) {
    return wmma::__float_to_tf32(x);
}
__device__ __forceinline__ unsigned long long fma2(unsigned long long a,
                                                   unsigned long long b,
                                                   unsigned long long c) {
    unsigned long long d;
    asm("fma.rn.f32x2 %0, %1, %2, %3;" : "=l"(d) : "l"(a), "l"(b), "l"(c));
    return d;
}
__device__ __forceinline__ float2 up2(unsigned long long u) {
    float2 f;
    asm("mov.b64 {%0, %1}, %2;" : "=f"(f.x), "=f"(f.y) : "l"(u));
    return f;
}

typedef wmma::fragment<wmma::matrix_a, 16, 16, 8, wmma::precision::tf32,
                       wmma::row_major> FragAR;
typedef wmma::fragment<wmma::matrix_a, 16, 16, 8, wmma::precision::tf32,
                       wmma::col_major> FragAC;
typedef wmma::fragment<wmma::matrix_b, 16, 16, 8, wmma::precision::tf32,
                       wmma::row_major> FragBR;
typedef wmma::fragment<wmma::accumulator, 16, 16, 8, float> FragC;

// attn smem: 3-stage ring. Stage = A(128x20 = 2560 fl) + B(16x68 = 1088 fl)
#define STAGE_FL 3648
#define AB_OFF   2560
#define SMEM_ATTN (3 * STAGE_FL * 4)   // 43776 B -> 4 CTAs/SM

// ---------------------------------------------------------------------------
__global__ void k_zero() {
    int i = blockIdx.x * 256 + threadIdx.x;
    g_rs[i] = 0.f;
    g_cs[i] = 0.f;
}

// tf32-rounded copies of Xs and Ys. 4,194,304 elems / (256*4) = 4096 blocks.
__global__ void k_prep(const float* __restrict__ Xs, const float* __restrict__ Ys) {
    size_t i = ((size_t)blockIdx.x * 256 + threadIdx.x) * 4;
    float4 x = *(const float4*)(Xs + i);
    float4 y = *(const float4*)(Ys + i);
    *(float4*)(g_Xr + i) =
        make_float4(tf32r(x.x), tf32r(x.y), tf32r(x.z), tf32r(x.w));
    *(float4*)(g_Yr + i) =
        make_float4(tf32r(y.x), tf32r(y.y), tf32r(y.z), tf32r(y.w));
}

// ---------------------------------------------------------------------------
// K1: Xc[r][e] = Xs[r][e] * tanh( sum_d W[r][d]*Aw[e][d] + Ab[e] )  (verified)
// ---------------------------------------------------------------------------
__global__ __launch_bounds__(256) void k_coeff(const float* __restrict__ W,
                                               const float* __restrict__ Aw,
                                               const float* __restrict__ Ab,
                                               const float* __restrict__ Xs) {
    const int tx = threadIdx.x, ty = threadIdx.y;
    const int tid = ty * 16 + tx;
    const int r0 = blockIdx.x * 64;

    __shared__ __align__(16) float Ws[64][32];
    __shared__ __align__(16) float Awt[32][132];

    float acc[4][8];
#pragma unroll
    for (int i = 0; i < 4; i++)
#pragma unroll
        for (int j = 0; j < 8; j++) acc[i][j] = 0.f;

    for (int k0 = 0; k0 < Dp; k0 += 32) {
#pragma unroll
        for (int it = 0; it < 2; it++) {
            int id = tid + it * 256;
            int r = id >> 3, q = id & 7;
            *(float4*)&Ws[r][q * 4] =
                *(const float4*)(W + (size_t)(r0 + r) * Dp + k0 + q * 4);
        }
#pragma unroll
        for (int it = 0; it < 4; it++) {
            int id = tid + it * 256;
            int e = id >> 3, q = id & 7;
            float4 v = *(const float4*)(Aw + (size_t)e * Dp + k0 + q * 4);
            Awt[q * 4 + 0][e] = v.x;
            Awt[q * 4 + 1][e] = v.y;
            Awt[q * 4 + 2][e] = v.z;
            Awt[q * 4 + 3][e] = v.w;
        }
        __syncthreads();
#pragma unroll
        for (int k = 0; k < 32; k++) {
            float w0 = Ws[ty * 4 + 0][k];
            float w1 = Ws[ty * 4 + 1][k];
            float w2 = Ws[ty * 4 + 2][k];
            float w3 = Ws[ty * 4 + 3][k];
            float4 a0 = *(const float4*)&Awt[k][tx * 8];
            float4 a1 = *(const float4*)&Awt[k][tx * 8 + 4];
            float av[8] = {a0.x, a0.y, a0.z, a0.w, a1.x, a1.y, a1.z, a1.w};
#pragma unroll
            for (int j = 0; j < 8; j++) {
                acc[0][j] = fmaf(w0, av[j], acc[0][j]);
                acc[1][j] = fmaf(w1, av[j], acc[1][j]);
                acc[2][j] = fmaf(w2, av[j], acc[2][j]);
                acc[3][j] = fmaf(w3, av[j], acc[3][j]);
            }
        }
        __syncthreads();
    }

    float abv[8];
    *(float4*)&abv[0] = *(const float4*)(Ab + tx * 8);
    *(float4*)&abv[4] = *(const float4*)(Ab + tx * 8 + 4);

#pragma unroll
    for (int i = 0; i < 4; i++) {
        int r = r0 + ty * 4 + i;
        const float* xr = Xs + (size_t)r * Dp + tx * 8;
        float4 x0 = *(const float4*)xr;
        float4 x1 = *(const float4*)(xr + 4);
        float c[8];
#pragma unroll
        for (int j = 0; j < 8; j++) c[j] = tanhf(acc[i][j] + abv[j]);
        float4 o0 = make_float4(x0.x * c[0], x0.y * c[1], x0.z * c[2], x0.w * c[3]);
        float4 o1 = make_float4(x1.x * c[4], x1.y * c[5], x1.z * c[6], x1.w * c[7]);
        float* dst = g_Xc + (size_t)r * Dp + tx * 8;
        *(float4*)dst = o0;
        *(float4*)(dst + 4) = o1;
    }
}

// ---------------------------------------------------------------------------
// K2 v2 (FFMA2, k-paired — no operand duplication): z = Xc @ Y^T.
// CTA tile 128n x 64m, micro 8n x 4m, K=128 in chunks of 8, double-buffered.
// A smem [128][10] (k-contig, pad 10); B smem float2 Bt[4][68] (k-pair, m-major).
// s out (exact fp32); P = tf32r(1+e^z) out; row/col sums of ROUNDED P.
// ---------------------------------------------------------------------------
__global__ __launch_bounds__(256, 2) void k_scores(const float* __restrict__ Ys,
                                                   float* __restrict__ out_s) {
    const int tx = threadIdx.x, ty = threadIdx.y;
    const int tid = ty * 16 + tx;
    const int mt = blockIdx.x, nt = blockIdx.y, b = blockIdx.z;

    __shared__ __align__(16) float As[2][128 * 10];   // row n: 10 fl, k in [0..7]
    __shared__ __align__(16) float2 Bt[2][4][68];     // [kp][m], pair (k even, k odd)
    __shared__ float scs[64];

    unsigned long long acc[8][4];
#pragma unroll
    for (int i = 0; i < 8; i++)
#pragma unroll
        for (int j = 0; j < 4; j++) acc[i][j] = 0ULL;

    const float* Xc = g_Xc + (size_t)(b * Np + nt * 128) * Dp;
    const float* Yb = Ys + (size_t)(b * Mp + mt * 64) * Dp;

    const int nl = tid >> 1, kq = tid & 1;   // A loader: 128 n x 2 kq
    if (tid < 64) scs[tid] = 0.f;

    // prologue: chunk 0
    {
        float4 va = *(const float4*)(Xc + (size_t)nl * Dp + kq * 4);
        float* ad = &As[0][nl * 10 + kq * 4];
        *(float2*)ad = make_float2(va.x, va.y);
        *(float2*)(ad + 2) = make_float2(va.z, va.w);
        if (tid < 128) {
            float4 vb = *(const float4*)(Yb + (size_t)nl * Dp + kq * 4);
            Bt[0][2 * kq + 0][nl] = make_float2(vb.x, vb.y);
            Bt[0][2 * kq + 1][nl] = make_float2(vb.z, vb.w);
        }
    }
    __syncthreads();

    const int NC = Dp / 8;  // 16
#pragma unroll 2
    for (int c = 0; c < NC; c++) {
        const int cur = c & 1;
        float4 pa, pb;
        const bool has = (c + 1 < NC);
        if (has) {
            pa = *(const float4*)(Xc + (size_t)nl * Dp + (c + 1) * 8 + kq * 4);
            if (tid < 128)
                pb = *(const float4*)(Yb + (size_t)nl * Dp + (c + 1) * 8 + kq * 4);
        }
#pragma unroll
        for (int kp = 0; kp < 4; kp++) {
            unsigned long long av[8];
#pragma unroll
            for (int i = 0; i < 8; i++)
                av[i] = *(const unsigned long long*)
                            &As[cur][(ty * 8 + i) * 10 + kp * 2];
            unsigned long long bv[4];
#pragma unroll
            for (int j = 0; j < 4; j++)
                bv[j] = *(const unsigned long long*)&Bt[cur][kp][j * 16 + tx];
#pragma unroll
            for (int i = 0; i < 8; i++)
#pragma unroll
                for (int j = 0; j < 4; j++)
                    acc[i][j] = fma2(av[i], bv[j], acc[i][j]);
        }
        if (has) {
            const int nx = cur ^ 1;
            float* ad = &As[nx][nl * 10 + kq * 4];
            *(float2*)ad = make_float2(pa.x, pa.y);
            *(float2*)(ad + 2) = make_float2(pa.z, pa.w);
            if (tid < 128) {
                Bt[nx][2 * kq + 0][nl] = make_float2(pb.x, pb.y);
                Bt[nx][2 * kq + 1][nl] = make_float2(pb.z, pb.w);
            }
        }
        __syncthreads();
    }

    // epilogue: z = pair-sum; s (exact fp32), rounded P, sums of rounded P.
    // n = nt*128 + ty*8 + i;  m = mt*64 + j*16 + tx.
    float csum[4];
#pragma unroll
    for (int j = 0; j < 4; j++) csum[j] = 0.f;

#pragma unroll
    for (int i = 0; i < 8; i++) {
        const size_t off =
            ((size_t)(b * Np + nt * 128 + ty * 8 + i)) * Mp + mt * 64;
        float rs = 0.f;
#pragma unroll
        for (int j = 0; j < 4; j++) {
            float2 zz = up2(acc[i][j]);
            float z = zz.x + zz.y;
            float p = 1.f + __expf(z);
            float pr = tf32r(p);
            out_s[off + j * 16 + tx] = __logf(p) - 0.5f;
            g_P[off + j * 16 + tx] = pr;
            rs += pr;
            csum[j] += pr;
        }
        rs += __shfl_xor_sync(0xFFFFFFFFu, rs, 1);
        rs += __shfl_xor_sync(0xFFFFFFFFu, rs, 2);
        rs += __shfl_xor_sync(0xFFFFFFFFu, rs, 4);
        rs += __shfl_xor_sync(0xFFFFFFFFu, rs, 8);
        if (tx == 0) atomicAdd(&g_rs[b * Np + nt * 128 + ty * 8 + i], rs);
    }

#pragma unroll
    for (int j = 0; j < 4; j++) atomicAdd(&scs[j * 16 + tx], csum[j]);
    __syncthreads();
    if (tid < 64) atomicAdd(&g_cs[b * Mp + mt * 64 + tid], scs[tid]);
}

// ---------------------------------------------------------------------------
// K3 (wmma tf32, latency-restructured — R12 WIN, unchanged):
//  128 threads / CTA (4 warps), CTA tile 128 rows x 64 cols (d half),
//  4 CTAs/SM, 3-stage ring, k-chunk 16.
// ---------------------------------------------------------------------------
__global__ __launch_bounds__(128, 4) void k_attn(float* __restrict__ out_x,
                                                 float* __restrict__ out_y) {
    extern __shared__ __align__(16) float smf[];
    const uint32_t sb = s2u(smf);
    const int t = threadIdx.x;
    const int w = t >> 5;
    const int rt = blockIdx.x;          // 128-row tile
    const int d0 = blockIdx.y * 64;     // d half
    const int b = blockIdx.z & 31;
    const int mode = blockIdx.z >> 5;

    const float* Pb = g_P + (size_t)b * Np * Mp;
    const float* Bsrc = mode ? (g_Xr + (size_t)b * Np * Dp)
                             : (g_Yr + (size_t)b * Mp * Dp);

    const int m0 = w * 32;              // warp row base (warp tile 32x64)

    FragC acc[2][4];
#pragma unroll
    for (int i = 0; i < 2; i++)
#pragma unroll
        for (int j = 0; j < 4; j++) wmma::fill_fragment(acc[i][j], 0.f);

    // stage layout: A @ +0 (mode0: [128][20]; mode1: [16][132]); B @ +2560 ([16][68])
    auto load_chunk = [&](int c, int f) {
        uint32_t Ad = sb + (uint32_t)(f * STAGE_FL) * 4;
        uint32_t Bd = Ad + AB_OFF * 4;
        if (mode == 0) {
#pragma unroll
            for (int o = 0; o < 4; o++) {
                int idx = t + o * 128;
                int row = idx >> 2, q = idx & 3;
                cpa16(Ad + (uint32_t)((row * 20 + q * 4) * 4),
                      Pb + (size_t)(rt * 128 + row) * Mp + c * 16 + q * 4);
            }
        } else {
#pragma unroll
            for (int o = 0; o < 4; o++) {
                int idx = t + o * 128;
                int kr = idx >> 5, mq = idx & 31;
                cpa16(Ad + (uint32_t)((kr * 132 + mq * 4) * 4),
                      Pb + (size_t)(c * 16 + kr) * Mp + rt * 128 + mq * 4);
            }
        }
#pragma unroll
        for (int o = 0; o < 2; o++) {
            int idx = t + o * 128;
            int kr = idx >> 4, dq = idx & 15;
            cpa16(Bd + (uint32_t)((kr * 68 + dq * 4) * 4),
                  Bsrc + (size_t)(c * 16 + kr) * Dp + d0 + dq * 4);
        }
        CP_COMMIT();
    };

    load_chunk(0, 0);
    load_chunk(1, 1);
    const int NC = 64;   // K = 1024 in chunks of 16
    for (int c = 0; c < NC; c++) {
        if (c + 1 < NC) CP_WAIT1(); else CP_WAIT0();
        __syncthreads();
        if (c + 2 < NC) load_chunk(c + 2, (c + 2) % 3);
        const float* As_ = smf + (c % 3) * STAGE_FL;
        const float* Bs_ = As_ + AB_OFF;
        if (mode == 0) {
#pragma unroll
            for (int s = 0; s < 2; s++) {
                FragAR af[2];
                FragBR bf[4];
#pragma unroll
                for (int i = 0; i < 2; i++)
                    wmma::load_matrix_sync(af[i], As_ + (m0 + i * 16) * 20 + s * 8, 20);
#pragma unroll
                for (int j = 0; j < 4; j++)
                    wmma::load_matrix_sync(bf[j], Bs_ + (s * 8) * 68 + j * 16, 68);
#pragma unroll
                for (int i = 0; i < 2; i++)
#pragma unroll
                    for (int j = 0; j < 4; j++)
                        wmma::mma_sync(acc[i][j], af[i], bf[j], acc[i][j]);
            }
        } else {
#pragma unroll
            for (int s = 0; s < 2; s++) {
                FragAC af[2];
                FragBR bf[4];
#pragma unroll
                for (int i = 0; i < 2; i++)
                    wmma::load_matrix_sync(af[i], As_ + (s * 8) * 132 + m0 + i * 16, 132);
#pragma unroll
                for (int j = 0; j < 4; j++)
                    wmma::load_matrix_sync(bf[j], Bs_ + (s * 8) * 68 + j * 16, 68);
#pragma unroll
                for (int i = 0; i < 2; i++)
#pragma unroll
                    for (int j = 0; j < 4; j++)
                        wmma::mma_sync(acc[i][j], af[i], bf[j], acc[i][j]);
            }
        }
    }
    __syncthreads();

    // stash to smem [128][68], then normalized coalesced write-out
#pragma unroll
    for (int i = 0; i < 2; i++)
#pragma unroll
        for (int j = 0; j < 4; j++)
            wmma::store_matrix_sync(smf + (m0 + i * 16) * 68 + j * 16,
                                    acc[i][j], 68, wmma::mem_row_major);
    __syncthreads();

    {
        const int r = t;   // each thread owns one output row (64 cols)
        const float inv =
            1.f / (mode ? g_cs[b * Mp + rt * 128 + r]
                        : g_rs[b * Np + rt * 128 + r]);
        const float* rowp = smf + r * 68;
        float* outp = (mode ? out_y : out_x) +
                      (size_t)(b * 1024 + rt * 128 + r) * Dp + d0;
#pragma unroll
        for (int j = 0; j < 16; j++) {
            float4 v = *(const float4*)(rowp + j * 4);
            *(float4*)(outp + j * 4) =
                make_float4(v.x * inv, v.y * inv, v.z * inv, v.w * inv);
        }
    }
}

// ---------------------------------------------------------------------------
extern "C" void kernel_launch(void* const* d_in, const int* in_sizes, int n_in,
                              void* d_out, int out_size) {
    const float* Xs = (const float*)d_in[0];
    const float* Ys = (const float*)d_in[1];
    const float* W  = (const float*)d_in[2];
    const float* Aw = (const float*)d_in[3];
    const float* Ab = (const float*)d_in[4];

    float* out = (float*)d_out;
    float* out_x = out;                               // [B,N,D]
    float* out_y = out_x + (size_t)Bp * Np * Dp;      // [B,M,D]
    float* out_s = out_y + (size_t)Bp * Mp * Dp;      // [B,N,M]

    cudaFuncSetAttribute(k_attn, cudaFuncAttributeMaxDynamicSharedMemorySize,
                         SMEM_ATTN);

    k_zero<<<128, 256>>>();
    k_prep<<<4096, 256>>>(Xs, Ys);
    k_coeff<<<(Bp * Np) / 64, dim3(16, 16)>>>(W, Aw, Ab, Xs);
    k_scores<<<dim3(16, 8, 32), dim3(16, 16)>>>(Ys, out_s);
    k_attn<<<dim3(8, 2, 64), 128, SMEM_ATTN>>>(out_x, out_y);
}

// round 14
// speedup vs baseline: 1.7503x; 1.0499x over previous
#include <cuda_runtime.h>
#include <mma.h>
#include <cstdint>

using namespace nvcuda;

#define Bp 32
#define Np 1024
#define Mp 1024
#define Dp 128

// Scratch (device globals; allocation is forbidden everywhere)
__device__ float g_Xc[Bp * Np * Dp];            // X * tanh(W@A^T+b)  [b][n][d] (fp32)
__device__ float g_Xr[Bp * Np * Dp];            // tf32-rounded Xs
__device__ float g_Yr[Bp * Mp * Dp];            // tf32-rounded Ys
__device__ float g_P[(size_t)Bp * Np * Mp];     // P = tf32r(1+e^z)   [b][n][m]
__device__ float g_rs[Bp * Np];                 // row sums of rounded P
__device__ float g_cs[Bp * Mp];                 // col sums of rounded P

// ---------------------------------------------------------------------------
__device__ __forceinline__ uint32_t s2u(const void* p) {
    uint32_t a;
    asm("{ .reg .u64 t; cvta.to.shared.u64 t, %1; cvt.u32.u64 %0, t; }"
        : "=r"(a) : "l"(p));
    return a;
}
__device__ __forceinline__ void cpa16(uint32_t d, const void* s) {
    asm volatile("cp.async.cg.shared.global [%0], [%1], 16;"
                 :: "r"(d), "l"(s) : "memory");
}
#define CP_COMMIT() asm volatile("cp.async.commit_group;" ::: "memory")
#define CP_WAIT1()  asm volatile("cp.async.wait_group 1;" ::: "memory")
#define CP_WAIT0()  asm volatile("cp.async.wait_group 0;" ::: "memory")

__device__ __forceinline__ float tf32r(float x) {
    return wmma::__float_to_tf32(x);
}
__device__ __forceinline__ unsigned long long fma2(unsigned long long a,
                                                   unsigned long long b,
                                                   unsigned long long c) {
    unsigned long long d;
    asm("fma.rn.f32x2 %0, %1, %2, %3;" : "=l"(d) : "l"(a), "l"(b), "l"(c));
    return d;
}
__device__ __forceinline__ float2 up2(unsigned long long u) {
    float2 f;
    asm("mov.b64 {%0, %1}, %2;" : "=f"(f.x), "=f"(f.y) : "l"(u));
    return f;
}

typedef wmma::fragment<wmma::matrix_a, 16, 16, 8, wmma::precision::tf32,
                       wmma::row_major> FragAR;
typedef wmma::fragment<wmma::matrix_a, 16, 16, 8, wmma::precision::tf32,
                       wmma::col_major> FragAC;
typedef wmma::fragment<wmma::matrix_b, 16, 16, 8, wmma::precision::tf32,
                       wmma::row_major> FragBR;
typedef wmma::fragment<wmma::accumulator, 16, 16, 8, float> FragC;

// attn smem: 3-stage ring. Stage = A(128x20 = 2560 fl) + B(16x68 = 1088 fl)
#define STAGE_FL 3648
#define AB_OFF   2560
#define SMEM_ATTN (3 * STAGE_FL * 4)   // 43776 B -> 4 CTAs/SM

// ---------------------------------------------------------------------------
__global__ void k_zero() {
    int i = blockIdx.x * 256 + threadIdx.x;
    g_rs[i] = 0.f;
    g_cs[i] = 0.f;
}

// tf32-rounded copies of Xs and Ys. 4,194,304 elems / (256*4) = 4096 blocks.
__global__ void k_prep(const float* __restrict__ Xs, const float* __restrict__ Ys) {
    size_t i = ((size_t)blockIdx.x * 256 + threadIdx.x) * 4;
    float4 x = *(const float4*)(Xs + i);
    float4 y = *(const float4*)(Ys + i);
    *(float4*)(g_Xr + i) =
        make_float4(tf32r(x.x), tf32r(x.y), tf32r(x.z), tf32r(x.w));
    *(float4*)(g_Yr + i) =
        make_float4(tf32r(y.x), tf32r(y.y), tf32r(y.z), tf32r(y.w));
}

// ---------------------------------------------------------------------------
// K1: Xc[r][e] = Xs[r][e] * tanh( sum_d W[r][d]*Aw[e][d] + Ab[e] )  (verified)
// ---------------------------------------------------------------------------
__global__ __launch_bounds__(256) void k_coeff(const float* __restrict__ W,
                                               const float* __restrict__ Aw,
                                               const float* __restrict__ Ab,
                                               const float* __restrict__ Xs) {
    const int tx = threadIdx.x, ty = threadIdx.y;
    const int tid = ty * 16 + tx;
    const int r0 = blockIdx.x * 64;

    __shared__ __align__(16) float Ws[64][32];
    __shared__ __align__(16) float Awt[32][132];

    float acc[4][8];
#pragma unroll
    for (int i = 0; i < 4; i++)
#pragma unroll
        for (int j = 0; j < 8; j++) acc[i][j] = 0.f;

    for (int k0 = 0; k0 < Dp; k0 += 32) {
#pragma unroll
        for (int it = 0; it < 2; it++) {
            int id = tid + it * 256;
            int r = id >> 3, q = id & 7;
            *(float4*)&Ws[r][q * 4] =
                *(const float4*)(W + (size_t)(r0 + r) * Dp + k0 + q * 4);
        }
#pragma unroll
        for (int it = 0; it < 4; it++) {
            int id = tid + it * 256;
            int e = id >> 3, q = id & 7;
            float4 v = *(const float4*)(Aw + (size_t)e * Dp + k0 + q * 4);
            Awt[q * 4 + 0][e] = v.x;
            Awt[q * 4 + 1][e] = v.y;
            Awt[q * 4 + 2][e] = v.z;
            Awt[q * 4 + 3][e] = v.w;
        }
        __syncthreads();
#pragma unroll
        for (int k = 0; k < 32; k++) {
            float w0 = Ws[ty * 4 + 0][k];
            float w1 = Ws[ty * 4 + 1][k];
            float w2 = Ws[ty * 4 + 2][k];
            float w3 = Ws[ty * 4 + 3][k];
            float4 a0 = *(const float4*)&Awt[k][tx * 8];
            float4 a1 = *(const float4*)&Awt[k][tx * 8 + 4];
            float av[8] = {a0.x, a0.y, a0.z, a0.w, a1.x, a1.y, a1.z, a1.w};
#pragma unroll
            for (int j = 0; j < 8; j++) {
                acc[0][j] = fmaf(w0, av[j], acc[0][j]);
                acc[1][j] = fmaf(w1, av[j], acc[1][j]);
                acc[2][j] = fmaf(w2, av[j], acc[2][j]);
                acc[3][j] = fmaf(w3, av[j], acc[3][j]);
            }
        }
        __syncthreads();
    }

    float abv[8];
    *(float4*)&abv[0] = *(const float4*)(Ab + tx * 8);
    *(float4*)&abv[4] = *(const float4*)(Ab + tx * 8 + 4);

#pragma unroll
    for (int i = 0; i < 4; i++) {
        int r = r0 + ty * 4 + i;
        const float* xr = Xs + (size_t)r * Dp + tx * 8;
        float4 x0 = *(const float4*)xr;
        float4 x1 = *(const float4*)(xr + 4);
        float c[8];
#pragma unroll
        for (int j = 0; j < 8; j++) c[j] = tanhf(acc[i][j] + abv[j]);
        float4 o0 = make_float4(x0.x * c[0], x0.y * c[1], x0.z * c[2], x0.w * c[3]);
        float4 o1 = make_float4(x1.x * c[4], x1.y * c[5], x1.z * c[6], x1.w * c[7]);
        float* dst = g_Xc + (size_t)r * Dp + tx * 8;
        *(float4*)dst = o0;
        *(float4*)(dst + 4) = o1;
    }
}

// ---------------------------------------------------------------------------
// K2 v3 (FFMA2 k-paired, latency-restructured):
//  128 threads / CTA, tile 64n x 64m, micro 8n x 4m, 4 CTAs/SM.
//  BOTH operands pair-interleaved float2 [kp][row] -> vectorized LDS,
//  no duplication. K=128 in chunks of 8, double-buffered.
//  s out (exact fp32); P = tf32r(1+e^z) out; row/col sums of ROUNDED P.
// ---------------------------------------------------------------------------
__global__ __launch_bounds__(128, 4) void k_scores(const float* __restrict__ Ys,
                                                   float* __restrict__ out_s) {
    const int tid = threadIdx.x;
    const int tx = tid & 15, ty = tid >> 4;     // tx: m group, ty: n group (0..7)
    const int mt = blockIdx.x, nt = blockIdx.y, b = blockIdx.z;

    __shared__ __align__(16) float2 As2[2][4][66];  // [kp][n-row], pair (2kp,2kp+1)
    __shared__ __align__(16) float2 Bt[2][4][66];   // [kp][m-row]
    __shared__ float scs[64];

    unsigned long long acc[8][4];
#pragma unroll
    for (int i = 0; i < 8; i++)
#pragma unroll
        for (int j = 0; j < 4; j++) acc[i][j] = 0ULL;

    const float* Xc = g_Xc + (size_t)(b * Np + nt * 64) * Dp;
    const float* Yb = Ys + (size_t)(b * Mp + mt * 64) * Dp;

    const int nl = tid >> 1, kq = tid & 1;   // loader: 64 rows x 2 k-quads
    if (tid < 64) scs[tid] = 0.f;

    // prologue: chunk 0
    {
        float4 va = *(const float4*)(Xc + (size_t)nl * Dp + kq * 4);
        float4 vb = *(const float4*)(Yb + (size_t)nl * Dp + kq * 4);
        As2[0][2 * kq + 0][nl] = make_float2(va.x, va.y);
        As2[0][2 * kq + 1][nl] = make_float2(va.z, va.w);
        Bt[0][2 * kq + 0][nl] = make_float2(vb.x, vb.y);
        Bt[0][2 * kq + 1][nl] = make_float2(vb.z, vb.w);
    }
    __syncthreads();

    const int NC = Dp / 8;  // 16
#pragma unroll 2
    for (int c = 0; c < NC; c++) {
        const int cur = c & 1;
        float4 pa, pb;
        const bool has = (c + 1 < NC);
        if (has) {
            pa = *(const float4*)(Xc + (size_t)nl * Dp + (c + 1) * 8 + kq * 4);
            pb = *(const float4*)(Yb + (size_t)nl * Dp + (c + 1) * 8 + kq * 4);
        }
#pragma unroll
        for (int kp = 0; kp < 4; kp++) {
            const ulonglong2* ap = (const ulonglong2*)&As2[cur][kp][ty * 8];
            ulonglong2 a01 = ap[0], a23 = ap[1], a45 = ap[2], a67 = ap[3];
            unsigned long long av[8] = {a01.x, a01.y, a23.x, a23.y,
                                        a45.x, a45.y, a67.x, a67.y};
            unsigned long long bv[4];
#pragma unroll
            for (int j = 0; j < 4; j++)
                bv[j] = *(const unsigned long long*)&Bt[cur][kp][j * 16 + tx];
#pragma unroll
            for (int i = 0; i < 8; i++)
#pragma unroll
                for (int j = 0; j < 4; j++)
                    acc[i][j] = fma2(av[i], bv[j], acc[i][j]);
        }
        if (has) {
            const int nx = cur ^ 1;
            As2[nx][2 * kq + 0][nl] = make_float2(pa.x, pa.y);
            As2[nx][2 * kq + 1][nl] = make_float2(pa.z, pa.w);
            Bt[nx][2 * kq + 0][nl] = make_float2(pb.x, pb.y);
            Bt[nx][2 * kq + 1][nl] = make_float2(pb.z, pb.w);
        }
        __syncthreads();
    }

    // epilogue: z = pair-sum; s (exact fp32), rounded P, sums of rounded P.
    // n = nt*64 + ty*8 + i;  m = mt*64 + j*16 + tx.
    float csum[4];
#pragma unroll
    for (int j = 0; j < 4; j++) csum[j] = 0.f;

#pragma unroll
    for (int i = 0; i < 8; i++) {
        const size_t off =
            ((size_t)(b * Np + nt * 64 + ty * 8 + i)) * Mp + mt * 64;
        float rs = 0.f;
#pragma unroll
        for (int j = 0; j < 4; j++) {
            float2 zz = up2(acc[i][j]);
            float z = zz.x + zz.y;
            float p = 1.f + __expf(z);
            float pr = tf32r(p);
            out_s[off + j * 16 + tx] = __logf(p) - 0.5f;
            g_P[off + j * 16 + tx] = pr;
            rs += pr;
            csum[j] += pr;
        }
        rs += __shfl_xor_sync(0xFFFFFFFFu, rs, 1);
        rs += __shfl_xor_sync(0xFFFFFFFFu, rs, 2);
        rs += __shfl_xor_sync(0xFFFFFFFFu, rs, 4);
        rs += __shfl_xor_sync(0xFFFFFFFFu, rs, 8);
        if (tx == 0) atomicAdd(&g_rs[b * Np + nt * 64 + ty * 8 + i], rs);
    }

#pragma unroll
    for (int j = 0; j < 4; j++) atomicAdd(&scs[j * 16 + tx], csum[j]);
    __syncthreads();
    if (tid < 64) atomicAdd(&g_cs[b * Mp + mt * 64 + tid], scs[tid]);
}

// ---------------------------------------------------------------------------
// K3 (wmma tf32, latency-restructured — R12 WIN, unchanged):
//  128 threads / CTA (4 warps), CTA tile 128 rows x 64 cols (d half),
//  4 CTAs/SM, 3-stage ring, k-chunk 16.
// ---------------------------------------------------------------------------
__global__ __launch_bounds__(128, 4) void k_attn(float* __restrict__ out_x,
                                                 float* __restrict__ out_y) {
    extern __shared__ __align__(16) float smf[];
    const uint32_t sb = s2u(smf);
    const int t = threadIdx.x;
    const int w = t >> 5;
    const int rt = blockIdx.x;          // 128-row tile
    const int d0 = blockIdx.y * 64;     // d half
    const int b = blockIdx.z & 31;
    const int mode = blockIdx.z >> 5;

    const float* Pb = g_P + (size_t)b * Np * Mp;
    const float* Bsrc = mode ? (g_Xr + (size_t)b * Np * Dp)
                             : (g_Yr + (size_t)b * Mp * Dp);

    const int m0 = w * 32;              // warp row base (warp tile 32x64)

    FragC acc[2][4];
#pragma unroll
    for (int i = 0; i < 2; i++)
#pragma unroll
        for (int j = 0; j < 4; j++) wmma::fill_fragment(acc[i][j], 0.f);

    // stage layout: A @ +0 (mode0: [128][20]; mode1: [16][132]); B @ +2560 ([16][68])
    auto load_chunk = [&](int c, int f) {
        uint32_t Ad = sb + (uint32_t)(f * STAGE_FL) * 4;
        uint32_t Bd = Ad + AB_OFF * 4;
        if (mode == 0) {
#pragma unroll
            for (int o = 0; o < 4; o++) {
                int idx = t + o * 128;
                int row = idx >> 2, q = idx & 3;
                cpa16(Ad + (uint32_t)((row * 20 + q * 4) * 4),
                      Pb + (size_t)(rt * 128 + row) * Mp + c * 16 + q * 4);
            }
        } else {
#pragma unroll
            for (int o = 0; o < 4; o++) {
                int idx = t + o * 128;
                int kr = idx >> 5, mq = idx & 31;
                cpa16(Ad + (uint32_t)((kr * 132 + mq * 4) * 4),
                      Pb + (size_t)(c * 16 + kr) * Mp + rt * 128 + mq * 4);
            }
        }
#pragma unroll
        for (int o = 0; o < 2; o++) {
            int idx = t + o * 128;
            int kr = idx >> 4, dq = idx & 15;
            cpa16(Bd + (uint32_t)((kr * 68 + dq * 4) * 4),
                  Bsrc + (size_t)(c * 16 + kr) * Dp + d0 + dq * 4);
        }
        CP_COMMIT();
    };

    load_chunk(0, 0);
    load_chunk(1, 1);
    const int NC = 64;   // K = 1024 in chunks of 16
    for (int c = 0; c < NC; c++) {
        if (c + 1 < NC) CP_WAIT1(); else CP_WAIT0();
        __syncthreads();
        if (c + 2 < NC) load_chunk(c + 2, (c + 2) % 3);
        const float* As_ = smf + (c % 3) * STAGE_FL;
        const float* Bs_ = As_ + AB_OFF;
        if (mode == 0) {
#pragma unroll
            for (int s = 0; s < 2; s++) {
                FragAR af[2];
                FragBR bf[4];
#pragma unroll
                for (int i = 0; i < 2; i++)
                    wmma::load_matrix_sync(af[i], As_ + (m0 + i * 16) * 20 + s * 8, 20);
#pragma unroll
                for (int j = 0; j < 4; j++)
                    wmma::load_matrix_sync(bf[j], Bs_ + (s * 8) * 68 + j * 16, 68);
#pragma unroll
                for (int i = 0; i < 2; i++)
#pragma unroll
                    for (int j = 0; j < 4; j++)
                        wmma::mma_sync(acc[i][j], af[i], bf[j], acc[i][j]);
            }
        } else {
#pragma unroll
            for (int s = 0; s < 2; s++) {
                FragAC af[2];
                FragBR bf[4];
#pragma unroll
                for (int i = 0; i < 2; i++)
                    wmma::load_matrix_sync(af[i], As_ + (s * 8) * 132 + m0 + i * 16, 132);
#pragma unroll
                for (int j = 0; j < 4; j++)
                    wmma::load_matrix_sync(bf[j], Bs_ + (s * 8) * 68 + j * 16, 68);
#pragma unroll
                for (int i = 0; i < 2; i++)
#pragma unroll
                    for (int j = 0; j < 4; j++)
                        wmma::mma_sync(acc[i][j], af[i], bf[j], acc[i][j]);
            }
        }
    }
    __syncthreads();

    // stash to smem [128][68], then normalized coalesced write-out
#pragma unroll
    for (int i = 0; i < 2; i++)
#pragma unroll
        for (int j = 0; j < 4; j++)
            wmma::store_matrix_sync(smf + (m0 + i * 16) * 68 + j * 16,
                                    acc[i][j], 68, wmma::mem_row_major);
    __syncthreads();

    {
        const int r = t;   // each thread owns one output row (64 cols)
        const float inv =
            1.f / (mode ? g_cs[b * Mp + rt * 128 + r]
                        : g_rs[b * Np + rt * 128 + r]);
        const float* rowp = smf + r * 68;
        float* outp = (mode ? out_y : out_x) +
                      (size_t)(b * 1024 + rt * 128 + r) * Dp + d0;
#pragma unroll
        for (int j = 0; j < 16; j++) {
            float4 v = *(const float4*)(rowp + j * 4);
            *(float4*)(outp + j * 4) =
                make_float4(v.x * inv, v.y * inv, v.z * inv, v.w * inv);
        }
    }
}

// ---------------------------------------------------------------------------
extern "C" void kernel_launch(void* const* d_in, const int* in_sizes, int n_in,
                              void* d_out, int out_size) {
    const float* Xs = (const float*)d_in[0];
    const float* Ys = (const float*)d_in[1];
    const float* W  = (const float*)d_in[2];
    const float* Aw = (const float*)d_in[3];
    const float* Ab = (const float*)d_in[4];

    float* out = (float*)d_out;
    float* out_x = out;                               // [B,N,D]
    float* out_y = out_x + (size_t)Bp * Np * Dp;      // [B,M,D]
    float* out_s = out_y + (size_t)Bp * Mp * Dp;      // [B,N,M]

    cudaFuncSetAttribute(k_attn, cudaFuncAttributeMaxDynamicSharedMemorySize,
                         SMEM_ATTN);

    k_zero<<<128, 256>>>();
    k_prep<<<4096, 256>>>(Xs, Ys);
    k_coeff<<<(Bp * Np) / 64, dim3(16, 16)>>>(W, Aw, Ab, Xs);
    k_scores<<<dim3(16, 16, 32), 128>>>(Ys, out_s);
    k_attn<<<dim3(8, 2, 64), 128, SMEM_ATTN>>>(out_x, out_y);
}